// round 11
// baseline (speedup 1.0000x reference)
#include <cuda_runtime.h>
#include <math.h>

// Problem constants
#define NBATCH 16
#define NC1 8
#define NC2 16
#define NM 63
#define NK2 32
#define NF (NM*NK2)  /* 2016 */
#define NPIX 16384   /* 128*128 */

// ---------------- device scratch ----------------
__device__ float2  g_Kf[128*NF];
__device__ float2  g_Ff[128*NF];
__device__ float2  g_Cf[256*NF];
__device__ float   g_u[256*NPIX];
__device__ float   g_v[256*NPIX];
__device__ float2  g_Ey[64*32];
__device__ float2  g_Ex[64*64];
__device__ float2  g_WxT[63*128];
__device__ float2  g_WyT[32*128];
__device__ float   g_MU[NF];
__device__ float   g_MV[NF];
__device__ int     g_I[120], g_J[120];

// ---------------- table init (parallel) ----------------
__global__ void k_init() {
    int tid = blockIdx.x*256 + threadIdx.x;
    int stride = gridDim.x*256;
    for (int idx = tid; idx < 64*32; idx += stride) {
        int y = idx >> 5, k2 = idx & 31;
        float s, c; sincospif(-2.0f * (float)(k2*y) / 64.0f, &s, &c);
        g_Ey[idx] = make_float2(c, s);
    }
    for (int idx = tid; idx < 64*64; idx += stride) {
        int m = idx >> 6, x = idx & 63; int k1 = m - 31;
        float s, c; sincospif(-2.0f * (float)(k1*x) / 64.0f, &s, &c);
        g_Ex[idx] = make_float2(c, s);
    }
    for (int idx = tid; idx < 63*128; idx += stride) {
        int m = idx >> 7, n1 = idx & 127; int k1 = m - 31;
        float s, c; sincospif(2.0f * (float)(k1*n1) / 128.0f, &s, &c);
        g_WxT[idx] = make_float2(c, s);
    }
    for (int idx = tid; idx < 32*128; idx += stride) {
        int k2 = idx >> 7, n2 = idx & 127;
        float s, c; sincospif(2.0f * (float)(k2*n2) / 128.0f, &s, &c);
        float sc = ((k2 == 0) ? 1.0f : 2.0f) * (2.0f / 16384.0f);
        g_WyT[idx] = make_float2(c * sc, s * sc);
    }
    for (int idx = tid; idx < NF; idx += stride) {
        int m = idx >> 5, k2 = idx & 31; int k1 = m - 31;
        float den = (float)(k1*k1 + k2*k2);
        if (den == 0.0f) den = 1.0f;
        g_MU[idx] =  (float)k2 / den;
        g_MV[idx] = -(float)k1 / den;
    }
    for (int p = tid; p < 120; p += stride) {
        int off = p, i = 0, cnt = 15;
        while (off >= cnt) { off -= cnt; i++; cnt--; }
        g_I[p] = i; g_J[p] = i + 1 + off;
    }
}

// ---------------- forward DFT (512 threads; fused D4 symmetrization) ----
__global__ void __launch_bounds__(512) k_fft64(const float* __restrict__ f,
                                               const float* __restrict__ kin) {
    __shared__ float  ss[4096];
    __shared__ float2 sA[2048];
    int ch = blockIdx.x;
    int t = threadIdx.x;
    bool isK = (ch < 128);
    const float* src = isK ? (kin + ch*4096) : (f + (ch-128)*4096);
    for (int i = t; i < 4096; i += 512) ss[i] = src[i];
    __syncthreads();
    if (isK) {
        float rv[8];
        #pragma unroll
        for (int r = 0; r < 8; r++) {
            int idx = t + 512*r;
            int a = idx >> 6, b = idx & 63;
            int na = (64 - a) & 63, nb = (64 - b) & 63;
            rv[r] = (ss[a*64 + b]  + ss[nb*64 + a] + ss[na*64 + nb] + ss[b*64 + na]
                   + ss[b*64 + a]  + ss[a*64 + nb] + ss[nb*64 + na] + ss[na*64 + b]) * 0.125f;
        }
        __syncthreads();
        #pragma unroll
        for (int r = 0; r < 8; r++) ss[t + 512*r] = rv[r];
        __syncthreads();
    }
    int k2 = t & 31, grp = t >> 5;
    {
        float2 acc[4];
        #pragma unroll
        for (int r = 0; r < 4; r++) acc[r] = make_float2(0.f, 0.f);
        for (int y = 0; y < 64; y++) {
            float2 e = g_Ey[y*32 + k2];
            #pragma unroll
            for (int r = 0; r < 4; r++) {
                float sv = ss[(grp*4 + r)*64 + y];
                acc[r].x = fmaf(sv, e.x, acc[r].x);
                acc[r].y = fmaf(sv, e.y, acc[r].y);
            }
        }
        #pragma unroll
        for (int r = 0; r < 4; r++) sA[(grp*4 + r)*32 + k2] = acc[r];
    }
    __syncthreads();
    {
        float2 acc[4];
        #pragma unroll
        for (int r = 0; r < 4; r++) acc[r] = make_float2(0.f, 0.f);
        for (int x = 0; x < 64; x++) {
            #pragma unroll
            for (int r = 0; r < 4; r++) {
                int m = grp*4 + r;
                float2 e = g_Ex[m*64 + x];
                float2 a = sA[x*32 + k2];
                acc[r].x = fmaf(e.x, a.x, fmaf(-e.y, a.y, acc[r].x));
                acc[r].y = fmaf(e.x, a.y, fmaf( e.y, a.x, acc[r].y));
            }
        }
        float2* dstF = isK ? (g_Kf + ch*NF) : (g_Ff + (ch-128)*NF);
        #pragma unroll
        for (int r = 0; r < 4; r++) {
            int m = grp*4 + r;
            if (m < 63) dstF[m*32 + k2] = acc[r];
        }
    }
}

// ---------------- channel contraction ----------------
__global__ void k_conv() {
    int idx = blockIdx.x * 256 + threadIdx.x;
    int mk = idx % NF;
    int bj = idx / NF;
    int b = bj >> 4, j = bj & 15;
    float2 acc = make_float2(0.f, 0.f);
    #pragma unroll
    for (int i = 0; i < 8; i++) {
        float2 Fv = g_Ff[(b*8 + i)*NF + mk];
        float2 Kv = g_Kf[(i*16 + j)*NF + mk];
        acc.x = fmaf(Fv.x, Kv.x, fmaf(-Fv.y, Kv.y, acc.x));
        acc.y = fmaf(Fv.x, Kv.y, fmaf( Fv.y, Kv.x, acc.y));
    }
    g_Cf[bj*NF + mk] = acc;
}

// ---------------- fused inverse transform: quarter-channel + smem twiddles -
// grid = 640 ch * 4 quarters, 128 threads.
// smem layout (bytes):
//   SD   [31*32 float4]  @ 0      (15872)
//   Zs   [32 float2]     @ 15872  (256)
//   Qs   [32*34 float2]  @ 16128  (8704)
//   Wxs  [31*16 float2]  @ 24832  (3968)   Wx slice for this quarter's n1h
//   Wys  [32*64 float2]  @ 28800  (16384)  Wy cols 0..63
//   Wy64 [32 float2]     @ 45184  (256)    Wy col 64
#define SM2_SD   0
#define SM2_Z    15872
#define SM2_Q    16128
#define SM2_WX   24832
#define SM2_WY   28800
#define SM2_W64  45184
#define SM2_TOT  45440

__global__ void __launch_bounds__(128, 5) k_itrans(float* __restrict__ out) {
    extern __shared__ char sm[];
    float4* SD   = (float4*)(sm + SM2_SD);
    float2* Zs   = (float2*)(sm + SM2_Z);
    float2* Qs   = (float2*)(sm + SM2_Q);    // [k2*34 + j]
    float2* Wxs  = (float2*)(sm + SM2_WX);   // [(k1-1)*16 + jl]
    float2* Wys  = (float2*)(sm + SM2_WY);   // [k2*64 + n2]
    float2* Wy64 = (float2*)(sm + SM2_W64);  // [k2]

    int t = threadIdx.x;
    int ch = blockIdx.x >> 2, qt = blockIdx.x & 3;
    const float2* src; float* dst; const float* mul = nullptr; float msgn = 1.0f;
    if (ch < 128) {
        src = g_Ff + ch*NF;
        int b = ch >> 3, c = ch & 7;
        dst = out + (size_t)(b*128 + c) * NPIX;
    } else if (ch < 384) {
        int c2 = ch - 128; src = g_Cf + c2*NF; dst = g_u + (size_t)c2*NPIX; mul = g_MU;
    } else {
        int c2 = ch - 384; src = g_Cf + c2*NF; dst = g_v + (size_t)c2*NPIX; mul = g_MV; msgn = -1.0f;
    }

    // stage twiddle slices into smem
    for (int i = t; i < 496; i += 128)
        Wxs[i] = g_WxT[(32 + (i >> 4))*128 + qt*16 + (i & 15)];
    for (int i = t; i < 2048; i += 128)
        Wys[i] = g_WyT[(i >> 6)*128 + (i & 63)];
    if (t < 32) Wy64[t] = g_WyT[t*128 + 64];

    // phase 1: build S/D from global
    for (int e = t; e < 992; e += 128) {
        int k1 = (e >> 5) + 1, k2 = e & 31;
        float2 gp = src[(31 + k1)*32 + k2];
        float2 gm = src[(31 - k1)*32 + k2];
        float2 a, b;
        if (mul) {
            float m = mul[(31 + k1)*32 + k2];
            a = make_float2(-m*gp.y, m*gp.x);
            float mm = msgn * m;
            b = make_float2(-mm*gm.y, mm*gm.x);
        } else {
            a = gp; b = gm;
        }
        SD[e] = make_float4(a.x + b.x, a.y + b.y, a.x - b.x, a.y - b.y);
    }
    if (t < 32) {
        float2 z = src[31*32 + t];
        if (mul) {
            float m = mul[31*32 + t];
            z = make_float2(-m*z.y, m*z.x);
        }
        Zs[t] = z;
    }
    __syncthreads();

    // phase 2a: Q[k2][n1=64] (qt==0 only)
    if (qt == 0 && t < 32) {
        float2 z = Zs[t];
        float pr = z.x, pi = z.y;
        #pragma unroll
        for (int k1 = 1; k1 < 32; k1++) {
            float4 sd = SD[(k1-1)*32 + t];
            float sgn = (k1 & 1) ? -1.0f : 1.0f;
            pr = fmaf(sgn, sd.x, pr);
            pi = fmaf(sgn, sd.y, pi);
        }
        Qs[t*34 + 32] = make_float2(pr, pi);
    }

    // phase 2b: stage1 — one n1h x 4 k2 per thread, pipelined, smem twiddles
    {
        int jl = t & 15, kg = t >> 4;
        int k2b = kg*4;
        float P[4], R[4], T[4], U[4];
        #pragma unroll
        for (int u = 0; u < 4; u++) { P[u]=0.f; R[u]=0.f; T[u]=0.f; U[u]=0.f; }
        float4 s0 = SD[k2b+0], s1 = SD[k2b+1], s2 = SD[k2b+2], s3 = SD[k2b+3];
        float2 w = Wxs[jl];
        #pragma unroll
        for (int k1 = 1; k1 <= 31; k1++) {
            float4 c0 = s0, c1 = s1, c2 = s2, c3 = s3;
            float2 wc = w;
            if (k1 < 31) {
                const float4* p = SD + k1*32 + k2b;
                s0 = p[0]; s1 = p[1]; s2 = p[2]; s3 = p[3];
                w = Wxs[k1*16 + jl];
            }
            P[0]=fmaf(wc.x,c0.x,P[0]); T[0]=fmaf(wc.x,c0.y,T[0]); U[0]=fmaf(wc.y,c0.z,U[0]); R[0]=fmaf(wc.y,c0.w,R[0]);
            P[1]=fmaf(wc.x,c1.x,P[1]); T[1]=fmaf(wc.x,c1.y,T[1]); U[1]=fmaf(wc.y,c1.z,U[1]); R[1]=fmaf(wc.y,c1.w,R[1]);
            P[2]=fmaf(wc.x,c2.x,P[2]); T[2]=fmaf(wc.x,c2.y,T[2]); U[2]=fmaf(wc.y,c2.z,U[2]); R[2]=fmaf(wc.y,c2.w,R[2]);
            P[3]=fmaf(wc.x,c3.x,P[3]); T[3]=fmaf(wc.x,c3.y,T[3]); U[3]=fmaf(wc.y,c3.z,U[3]); R[3]=fmaf(wc.y,c3.w,R[3]);
        }
        #pragma unroll
        for (int u = 0; u < 4; u++) {
            int k2 = k2b + u;
            float2 z = Zs[k2];
            Qs[k2*34 + jl]      = make_float2(z.x + P[u] - R[u], z.y + T[u] + U[u]);
            Qs[k2*34 + 16 + jl] = make_float2(z.x + P[u] + R[u], z.y + T[u] - U[u]);
        }
    }
    __syncthreads();

    // phase 3a: n2 = 64 column
    if (t < 32) {
        int j = t;
        int n1row = (j < 16) ? (qt*16 + j) : ((128 - (qt*16 + j - 16)) & 127);
        float acc = 0.f;
        #pragma unroll
        for (int k2 = 0; k2 < 32; k2++)
            acc = fmaf(Wy64[k2].x, Qs[k2*34 + j].x, acc);
        dst[n1row*128 + 64] = acc;
    } else if (qt == 0 && t == 32) {
        float acc = 0.f;
        #pragma unroll
        for (int k2 = 0; k2 < 32; k2++)
            acc = fmaf(Wy64[k2].x, Qs[k2*34 + 32].x, acc);
        dst[64*128 + 64] = acc;
    }

    // phase 3b: stage2 — pipelined over k2, float4 smem loads
    {
        int tx = t & 15, ty = t >> 4;
        int jb = ty*4;
        float E[4][4], O[4][4];
        #pragma unroll
        for (int u = 0; u < 4; u++)
            #pragma unroll
            for (int j = 0; j < 4; j++) { E[u][j] = 0.f; O[u][j] = 0.f; }
        float4 q01 = *(const float4*)&Qs[jb];
        float4 q23 = *(const float4*)&Qs[jb + 2];
        float4 wa  = *(const float4*)&Wys[tx*4];
        float4 wb  = *(const float4*)&Wys[tx*4 + 2];
        #pragma unroll
        for (int k2 = 0; k2 < 32; k2++) {
            float4 qc01 = q01, qc23 = q23, wac = wa, wbc = wb;
            if (k2 < 31) {
                q01 = *(const float4*)&Qs[(k2+1)*34 + jb];
                q23 = *(const float4*)&Qs[(k2+1)*34 + jb + 2];
                wa  = *(const float4*)&Wys[(k2+1)*64 + tx*4];
                wb  = *(const float4*)&Wys[(k2+1)*64 + tx*4 + 2];
            }
            E[0][0]=fmaf(qc01.x,wac.x,E[0][0]); O[0][0]=fmaf(qc01.y,wac.y,O[0][0]);
            E[0][1]=fmaf(qc01.x,wac.z,E[0][1]); O[0][1]=fmaf(qc01.y,wac.w,O[0][1]);
            E[0][2]=fmaf(qc01.x,wbc.x,E[0][2]); O[0][2]=fmaf(qc01.y,wbc.y,O[0][2]);
            E[0][3]=fmaf(qc01.x,wbc.z,E[0][3]); O[0][3]=fmaf(qc01.y,wbc.w,O[0][3]);
            E[1][0]=fmaf(qc01.z,wac.x,E[1][0]); O[1][0]=fmaf(qc01.w,wac.y,O[1][0]);
            E[1][1]=fmaf(qc01.z,wac.z,E[1][1]); O[1][1]=fmaf(qc01.w,wac.w,O[1][1]);
            E[1][2]=fmaf(qc01.z,wbc.x,E[1][2]); O[1][2]=fmaf(qc01.w,wbc.y,O[1][2]);
            E[1][3]=fmaf(qc01.z,wbc.z,E[1][3]); O[1][3]=fmaf(qc01.w,wbc.w,O[1][3]);
            E[2][0]=fmaf(qc23.x,wac.x,E[2][0]); O[2][0]=fmaf(qc23.y,wac.y,O[2][0]);
            E[2][1]=fmaf(qc23.x,wac.z,E[2][1]); O[2][1]=fmaf(qc23.y,wac.w,O[2][1]);
            E[2][2]=fmaf(qc23.x,wbc.x,E[2][2]); O[2][2]=fmaf(qc23.y,wbc.y,O[2][2]);
            E[2][3]=fmaf(qc23.x,wbc.z,E[2][3]); O[2][3]=fmaf(qc23.y,wbc.w,O[2][3]);
            E[3][0]=fmaf(qc23.z,wac.x,E[3][0]); O[3][0]=fmaf(qc23.w,wac.y,O[3][0]);
            E[3][1]=fmaf(qc23.z,wac.z,E[3][1]); O[3][1]=fmaf(qc23.w,wac.w,O[3][1]);
            E[3][2]=fmaf(qc23.z,wbc.x,E[3][2]); O[3][2]=fmaf(qc23.w,wbc.y,O[3][2]);
            E[3][3]=fmaf(qc23.z,wbc.z,E[3][3]); O[3][3]=fmaf(qc23.w,wbc.w,O[3][3]);
        }
        #pragma unroll
        for (int u = 0; u < 4; u++) {
            int j = jb + u;
            int n1row = (j < 16) ? (qt*16 + j) : ((128 - (qt*16 + j - 16)) & 127);
            float* row = dst + n1row*128;
            *(float4*)(row + tx*4) = make_float4(E[u][0]-O[u][0], E[u][1]-O[u][1],
                                                 E[u][2]-O[u][2], E[u][3]-O[u][3]);
            #pragma unroll
            for (int jj = 0; jj < 4; jj++)
                row[(128 - (tx*4 + jj)) & 127] = E[u][jj] + O[u][jj];
        }
    }

    // phase 3c: output row n1 = 64 (qt==0 only)
    if (qt == 0) {
        int n2 = t;
        float acc = 0.f;
        #pragma unroll 4
        for (int k2 = 0; k2 < 32; k2++) {
            float2 q = Qs[k2*34 + 32];
            float2 w = g_WyT[k2*128 + n2];
            acc = fmaf(q.x, w.x, fmaf(-q.y, w.y, acc));
        }
        if (n2 != 64) dst[64*128 + n2] = acc;
    }
}

// ---------------- cross products (vectorized stores) ----------------
__global__ void __launch_bounds__(128) k_cross(float* __restrict__ out) {
    __shared__ float us[16*128], vs[16*128];
    int b = blockIdx.x >> 7, n1 = blockIdx.x & 127;
    int t = threadIdx.x;
    for (int i = t; i < 16*128; i += 128) {
        int c = i >> 7, n2 = i & 127;
        us[i] = g_u[((size_t)(b*16 + c)*128 + n1)*128 + n2];
        vs[i] = g_v[((size_t)(b*16 + c)*128 + n1)*128 + n2];
    }
    __syncthreads();
    int q = t & 31, g = t >> 5;
    float* obase = out + ((size_t)b*128 + 8)*NPIX + n1*128 + q*4;
    #pragma unroll 2
    for (int pp = 0; pp < 30; pp++) {
        int p = g*30 + pp;
        int i = g_I[p], j = g_J[p];
        float4 ui = *(float4*)&us[i*128 + q*4];
        float4 vj = *(float4*)&vs[j*128 + q*4];
        float4 uj = *(float4*)&us[j*128 + q*4];
        float4 vi = *(float4*)&vs[i*128 + q*4];
        float4 r;
        r.x = ui.x*vj.x - uj.x*vi.x;
        r.y = ui.y*vj.y - uj.y*vi.y;
        r.z = ui.z*vj.z - uj.z*vi.z;
        r.w = ui.w*vj.w - uj.w*vi.w;
        *(float4*)(obase + (size_t)p*NPIX) = r;
    }
}

// ---------------- launch ----------------
extern "C" void kernel_launch(void* const* d_in, const int* in_sizes, int n_in,
                              void* d_out, int out_size) {
    const float* f    = (const float*)d_in[0];   // [16,8,64,64]
    const float* kern = (const float*)d_in[1];   // [1,8,16,64,64]
    float* out = (float*)d_out;                  // [16,128,128,128]
    (void)in_sizes; (void)n_in; (void)out_size;

    cudaFuncSetAttribute(k_itrans, cudaFuncAttributeMaxDynamicSharedMemorySize, SM2_TOT);

    k_init   <<<40,   256>>>();
    k_fft64  <<<256,  512>>>(f, kern);
    k_conv   <<<2016, 256>>>();
    k_itrans <<<2560, 128, SM2_TOT>>>(out);
    k_cross  <<<2048, 128>>>(out);
}

// round 12
// speedup vs baseline: 1.1548x; 1.1548x over previous
#include <cuda_runtime.h>
#include <math.h>

// Problem constants
#define NBATCH 16
#define NC1 8
#define NC2 16
#define NM 63
#define NK2 32
#define NF (NM*NK2)  /* 2016 */
#define NPIX 16384   /* 128*128 */

// ---------------- device scratch ----------------
__device__ float2  g_Kf[128*NF];
__device__ float2  g_Ff[128*NF];
__device__ float2  g_Cf[256*NF];
__device__ float   g_u[256*NPIX];
__device__ float   g_v[256*NPIX];
__device__ float2  g_Ey[64*32];
__device__ float2  g_Ex[64*64];
__device__ float2  g_WxT[63*128];
__device__ float2  g_WyT[32*128];
__device__ float   g_MU[NF];
__device__ float   g_MV[NF];
__device__ int     g_I[120], g_J[120];

// ---------------- table init (parallel) ----------------
__global__ void k_init() {
    int tid = blockIdx.x*256 + threadIdx.x;
    int stride = gridDim.x*256;
    for (int idx = tid; idx < 64*32; idx += stride) {
        int y = idx >> 5, k2 = idx & 31;
        float s, c; sincospif(-2.0f * (float)(k2*y) / 64.0f, &s, &c);
        g_Ey[idx] = make_float2(c, s);
    }
    for (int idx = tid; idx < 64*64; idx += stride) {
        int m = idx >> 6, x = idx & 63; int k1 = m - 31;
        float s, c; sincospif(-2.0f * (float)(k1*x) / 64.0f, &s, &c);
        g_Ex[idx] = make_float2(c, s);
    }
    for (int idx = tid; idx < 63*128; idx += stride) {
        int m = idx >> 7, n1 = idx & 127; int k1 = m - 31;
        float s, c; sincospif(2.0f * (float)(k1*n1) / 128.0f, &s, &c);
        g_WxT[idx] = make_float2(c, s);
    }
    for (int idx = tid; idx < 32*128; idx += stride) {
        int k2 = idx >> 7, n2 = idx & 127;
        float s, c; sincospif(2.0f * (float)(k2*n2) / 128.0f, &s, &c);
        float sc = ((k2 == 0) ? 1.0f : 2.0f) * (2.0f / 16384.0f);
        g_WyT[idx] = make_float2(c * sc, s * sc);
    }
    for (int idx = tid; idx < NF; idx += stride) {
        int m = idx >> 5, k2 = idx & 31; int k1 = m - 31;
        float den = (float)(k1*k1 + k2*k2);
        if (den == 0.0f) den = 1.0f;
        g_MU[idx] =  (float)k2 / den;
        g_MV[idx] = -(float)k1 / den;
    }
    for (int p = tid; p < 120; p += stride) {
        int off = p, i = 0, cnt = 15;
        while (off >= cnt) { off -= cnt; i++; cnt--; }
        g_I[p] = i; g_J[p] = i + 1 + off;
    }
}

// ---------------- forward DFT (512 threads; fused D4 symmetrization) ----
__global__ void __launch_bounds__(512) k_fft64(const float* __restrict__ f,
                                               const float* __restrict__ kin) {
    __shared__ float  ss[4096];
    __shared__ float2 sA[2048];
    int ch = blockIdx.x;
    int t = threadIdx.x;
    bool isK = (ch < 128);
    const float* src = isK ? (kin + ch*4096) : (f + (ch-128)*4096);
    for (int i = t; i < 4096; i += 512) ss[i] = src[i];
    __syncthreads();
    if (isK) {
        float rv[8];
        #pragma unroll
        for (int r = 0; r < 8; r++) {
            int idx = t + 512*r;
            int a = idx >> 6, b = idx & 63;
            int na = (64 - a) & 63, nb = (64 - b) & 63;
            rv[r] = (ss[a*64 + b]  + ss[nb*64 + a] + ss[na*64 + nb] + ss[b*64 + na]
                   + ss[b*64 + a]  + ss[a*64 + nb] + ss[nb*64 + na] + ss[na*64 + b]) * 0.125f;
        }
        __syncthreads();
        #pragma unroll
        for (int r = 0; r < 8; r++) ss[t + 512*r] = rv[r];
        __syncthreads();
    }
    int k2 = t & 31, grp = t >> 5;
    {
        float2 acc[4];
        #pragma unroll
        for (int r = 0; r < 4; r++) acc[r] = make_float2(0.f, 0.f);
        for (int y = 0; y < 64; y++) {
            float2 e = g_Ey[y*32 + k2];
            #pragma unroll
            for (int r = 0; r < 4; r++) {
                float sv = ss[(grp*4 + r)*64 + y];
                acc[r].x = fmaf(sv, e.x, acc[r].x);
                acc[r].y = fmaf(sv, e.y, acc[r].y);
            }
        }
        #pragma unroll
        for (int r = 0; r < 4; r++) sA[(grp*4 + r)*32 + k2] = acc[r];
    }
    __syncthreads();
    {
        float2 acc[4];
        #pragma unroll
        for (int r = 0; r < 4; r++) acc[r] = make_float2(0.f, 0.f);
        for (int x = 0; x < 64; x++) {
            #pragma unroll
            for (int r = 0; r < 4; r++) {
                int m = grp*4 + r;
                float2 e = g_Ex[m*64 + x];
                float2 a = sA[x*32 + k2];
                acc[r].x = fmaf(e.x, a.x, fmaf(-e.y, a.y, acc[r].x));
                acc[r].y = fmaf(e.x, a.y, fmaf( e.y, a.x, acc[r].y));
            }
        }
        float2* dstF = isK ? (g_Kf + ch*NF) : (g_Ff + (ch-128)*NF);
        #pragma unroll
        for (int r = 0; r < 4; r++) {
            int m = grp*4 + r;
            if (m < 63) dstF[m*32 + k2] = acc[r];
        }
    }
}

// ---------------- channel contraction ----------------
__global__ void k_conv() {
    int idx = blockIdx.x * 256 + threadIdx.x;
    int mk = idx % NF;
    int bj = idx / NF;
    int b = bj >> 4, j = bj & 15;
    float2 acc = make_float2(0.f, 0.f);
    #pragma unroll
    for (int i = 0; i < 8; i++) {
        float2 Fv = g_Ff[(b*8 + i)*NF + mk];
        float2 Kv = g_Kf[(i*16 + j)*NF + mk];
        acc.x = fmaf(Fv.x, Kv.x, fmaf(-Fv.y, Kv.y, acc.x));
        acc.y = fmaf(Fv.x, Kv.y, fmaf( Fv.y, Kv.x, acc.y));
    }
    g_Cf[bj*NF + mk] = acc;
}

// ---------------- fused inverse transform: quarter-channel (R8 shape) ------
// grid = 640 ch * 4 quarters, 128 threads, 5 CTA/SM.
// Stage1 twiddles via complex recurrence (no per-iter LDG).
#define SM2_SD   0
#define SM2_Z    15872
#define SM2_Q    16128
#define SM2_TOT  (16128 + 8704)

__global__ void __launch_bounds__(128, 5) k_itrans(float* __restrict__ out) {
    extern __shared__ char sm[];
    float4* SD = (float4*)(sm + SM2_SD);      // [(k1-1)*32 + k2]
    float2* Zs = (float2*)(sm + SM2_Z);
    float2* Qs = (float2*)(sm + SM2_Q);       // [k2*34 + j]

    int t = threadIdx.x;
    int ch = blockIdx.x >> 2, qt = blockIdx.x & 3;
    const float2* src; float* dst; const float* mul = nullptr; float msgn = 1.0f;
    if (ch < 128) {
        src = g_Ff + ch*NF;
        int b = ch >> 3, c = ch & 7;
        dst = out + (size_t)(b*128 + c) * NPIX;
    } else if (ch < 384) {
        int c2 = ch - 128; src = g_Cf + c2*NF; dst = g_u + (size_t)c2*NPIX; mul = g_MU;
    } else {
        int c2 = ch - 384; src = g_Cf + c2*NF; dst = g_v + (size_t)c2*NPIX; mul = g_MV; msgn = -1.0f;
    }

    // phase 1: build S/D from global
    for (int e = t; e < 992; e += 128) {
        int k1 = (e >> 5) + 1, k2 = e & 31;
        float2 gp = src[(31 + k1)*32 + k2];
        float2 gm = src[(31 - k1)*32 + k2];
        float2 a, b;
        if (mul) {
            float m = mul[(31 + k1)*32 + k2];
            a = make_float2(-m*gp.y, m*gp.x);
            float mm = msgn * m;
            b = make_float2(-mm*gm.y, mm*gm.x);
        } else {
            a = gp; b = gm;
        }
        SD[e] = make_float4(a.x + b.x, a.y + b.y, a.x - b.x, a.y - b.y);
    }
    if (t < 32) {
        float2 z = src[31*32 + t];
        if (mul) {
            float m = mul[31*32 + t];
            z = make_float2(-m*z.y, m*z.x);
        }
        Zs[t] = z;
    }
    __syncthreads();

    // phase 2a: Q[k2][n1=64] (qt==0 only)
    if (qt == 0 && t < 32) {
        float2 z = Zs[t];
        float pr = z.x, pi = z.y;
        #pragma unroll
        for (int k1 = 1; k1 < 32; k1++) {
            float4 sd = SD[(k1-1)*32 + t];
            float sgn = (k1 & 1) ? -1.0f : 1.0f;
            pr = fmaf(sgn, sd.x, pr);
            pi = fmaf(sgn, sd.y, pi);
        }
        Qs[t*34 + 32] = make_float2(pr, pi);
    }

    // phase 2b: stage1 — one n1h x 4 k2; w via recurrence, SD pipelined
    {
        int jl = t & 15, kg = t >> 4, k2b = kg*4;
        int n1 = qt*16 + jl;
        float P[4], R[4], T[4], U[4];
        #pragma unroll
        for (int u = 0; u < 4; u++) { P[u]=0.f; R[u]=0.f; T[u]=0.f; U[u]=0.f; }
        float2 step = g_WxT[32*128 + n1];   // e^{2*pi*i*n1/128}
        float2 w = step;
        float4 s0 = SD[k2b+0], s1 = SD[k2b+1], s2 = SD[k2b+2], s3 = SD[k2b+3];
        #pragma unroll
        for (int k1 = 1; k1 <= 31; k1++) {
            float4 c0 = s0, c1 = s1, c2 = s2, c3 = s3;
            float2 wc = w;
            if (k1 < 31) {
                const float4* p = SD + k1*32 + k2b;
                s0 = p[0]; s1 = p[1]; s2 = p[2]; s3 = p[3];
                // advance twiddle: w *= step
                float wx = fmaf(wc.x, step.x, -wc.y*step.y);
                float wy = fmaf(wc.x, step.y,  wc.y*step.x);
                w = make_float2(wx, wy);
            }
            P[0]=fmaf(wc.x,c0.x,P[0]); T[0]=fmaf(wc.x,c0.y,T[0]); U[0]=fmaf(wc.y,c0.z,U[0]); R[0]=fmaf(wc.y,c0.w,R[0]);
            P[1]=fmaf(wc.x,c1.x,P[1]); T[1]=fmaf(wc.x,c1.y,T[1]); U[1]=fmaf(wc.y,c1.z,U[1]); R[1]=fmaf(wc.y,c1.w,R[1]);
            P[2]=fmaf(wc.x,c2.x,P[2]); T[2]=fmaf(wc.x,c2.y,T[2]); U[2]=fmaf(wc.y,c2.z,U[2]); R[2]=fmaf(wc.y,c2.w,R[2]);
            P[3]=fmaf(wc.x,c3.x,P[3]); T[3]=fmaf(wc.x,c3.y,T[3]); U[3]=fmaf(wc.y,c3.z,U[3]); R[3]=fmaf(wc.y,c3.w,R[3]);
        }
        #pragma unroll
        for (int u = 0; u < 4; u++) {
            int k2 = k2b + u;
            float2 z = Zs[k2];
            Qs[k2*34 + jl]      = make_float2(z.x + P[u] - R[u], z.y + T[u] + U[u]);
            Qs[k2*34 + 16 + jl] = make_float2(z.x + P[u] + R[u], z.y + T[u] - U[u]);
        }
    }
    __syncthreads();

    // phase 3a: n2 = 64 column
    if (t < 32) {
        int j = t;
        int n1row = (j < 16) ? (qt*16 + j) : ((128 - (qt*16 + j - 16)) & 127);
        float acc = 0.f;
        #pragma unroll
        for (int k2 = 0; k2 < 32; k2++)
            acc = fmaf(g_WyT[k2*128 + 64].x, Qs[k2*34 + j].x, acc);
        dst[n1row*128 + 64] = acc;
    } else if (qt == 0 && t == 32) {
        float acc = 0.f;
        #pragma unroll
        for (int k2 = 0; k2 < 32; k2++)
            acc = fmaf(g_WyT[k2*128 + 64].x, Qs[k2*34 + 32].x, acc);
        dst[64*128 + 64] = acc;
    }

    // phase 3b: stage2 — software-pipelined over k2, float4 Q loads
    {
        int tx = t & 15, ty = t >> 4;
        int jb = ty*4;
        float E[4][4], O[4][4];
        #pragma unroll
        for (int u = 0; u < 4; u++)
            #pragma unroll
            for (int j = 0; j < 4; j++) { E[u][j] = 0.f; O[u][j] = 0.f; }
        float4 q01 = *(const float4*)&Qs[jb];
        float4 q23 = *(const float4*)&Qs[jb + 2];
        float4 wa  = *(const float4*)&g_WyT[tx*4];
        float4 wb  = *(const float4*)&g_WyT[tx*4 + 2];
        #pragma unroll
        for (int k2 = 0; k2 < 32; k2++) {
            float4 qc01 = q01, qc23 = q23, wac = wa, wbc = wb;
            if (k2 < 31) {
                q01 = *(const float4*)&Qs[(k2+1)*34 + jb];
                q23 = *(const float4*)&Qs[(k2+1)*34 + jb + 2];
                wa  = *(const float4*)&g_WyT[(k2+1)*128 + tx*4];
                wb  = *(const float4*)&g_WyT[(k2+1)*128 + tx*4 + 2];
            }
            E[0][0]=fmaf(qc01.x,wac.x,E[0][0]); O[0][0]=fmaf(qc01.y,wac.y,O[0][0]);
            E[0][1]=fmaf(qc01.x,wac.z,E[0][1]); O[0][1]=fmaf(qc01.y,wac.w,O[0][1]);
            E[0][2]=fmaf(qc01.x,wbc.x,E[0][2]); O[0][2]=fmaf(qc01.y,wbc.y,O[0][2]);
            E[0][3]=fmaf(qc01.x,wbc.z,E[0][3]); O[0][3]=fmaf(qc01.y,wbc.w,O[0][3]);
            E[1][0]=fmaf(qc01.z,wac.x,E[1][0]); O[1][0]=fmaf(qc01.w,wac.y,O[1][0]);
            E[1][1]=fmaf(qc01.z,wac.z,E[1][1]); O[1][1]=fmaf(qc01.w,wac.w,O[1][1]);
            E[1][2]=fmaf(qc01.z,wbc.x,E[1][2]); O[1][2]=fmaf(qc01.w,wbc.y,O[1][2]);
            E[1][3]=fmaf(qc01.z,wbc.z,E[1][3]); O[1][3]=fmaf(qc01.w,wbc.w,O[1][3]);
            E[2][0]=fmaf(qc23.x,wac.x,E[2][0]); O[2][0]=fmaf(qc23.y,wac.y,O[2][0]);
            E[2][1]=fmaf(qc23.x,wac.z,E[2][1]); O[2][1]=fmaf(qc23.y,wac.w,O[2][1]);
            E[2][2]=fmaf(qc23.x,wbc.x,E[2][2]); O[2][2]=fmaf(qc23.y,wbc.y,O[2][2]);
            E[2][3]=fmaf(qc23.x,wbc.z,E[2][3]); O[2][3]=fmaf(qc23.y,wbc.w,O[2][3]);
            E[3][0]=fmaf(qc23.z,wac.x,E[3][0]); O[3][0]=fmaf(qc23.w,wac.y,O[3][0]);
            E[3][1]=fmaf(qc23.z,wac.z,E[3][1]); O[3][1]=fmaf(qc23.w,wac.w,O[3][1]);
            E[3][2]=fmaf(qc23.z,wbc.x,E[3][2]); O[3][2]=fmaf(qc23.w,wbc.y,O[3][2]);
            E[3][3]=fmaf(qc23.z,wbc.z,E[3][3]); O[3][3]=fmaf(qc23.w,wbc.w,O[3][3]);
        }
        #pragma unroll
        for (int u = 0; u < 4; u++) {
            int j = jb + u;
            int n1row = (j < 16) ? (qt*16 + j) : ((128 - (qt*16 + j - 16)) & 127);
            float* row = dst + n1row*128;
            *(float4*)(row + tx*4) = make_float4(E[u][0]-O[u][0], E[u][1]-O[u][1],
                                                 E[u][2]-O[u][2], E[u][3]-O[u][3]);
            #pragma unroll
            for (int jj = 0; jj < 4; jj++)
                row[(128 - (tx*4 + jj)) & 127] = E[u][jj] + O[u][jj];
        }
    }

    // phase 3c: output row n1 = 64 (qt==0 only)
    if (qt == 0) {
        int n2 = t;
        float acc = 0.f;
        #pragma unroll 4
        for (int k2 = 0; k2 < 32; k2++) {
            float2 q = Qs[k2*34 + 32];
            float2 w = g_WyT[k2*128 + n2];
            acc = fmaf(q.x, w.x, fmaf(-q.y, w.y, acc));
        }
        if (n2 != 64) dst[64*128 + n2] = acc;
    }
}

// ---------------- cross products (streaming stores) ----------------
__global__ void __launch_bounds__(128) k_cross(float* __restrict__ out) {
    __shared__ float us[16*128], vs[16*128];
    int b = blockIdx.x >> 7, n1 = blockIdx.x & 127;
    int t = threadIdx.x;
    for (int i = t; i < 16*128; i += 128) {
        int c = i >> 7, n2 = i & 127;
        us[i] = g_u[((size_t)(b*16 + c)*128 + n1)*128 + n2];
        vs[i] = g_v[((size_t)(b*16 + c)*128 + n1)*128 + n2];
    }
    __syncthreads();
    int q = t & 31, g = t >> 5;
    float* obase = out + ((size_t)b*128 + 8)*NPIX + n1*128 + q*4;
    #pragma unroll 2
    for (int pp = 0; pp < 30; pp++) {
        int p = g*30 + pp;
        int i = g_I[p], j = g_J[p];
        float4 ui = *(float4*)&us[i*128 + q*4];
        float4 vj = *(float4*)&vs[j*128 + q*4];
        float4 uj = *(float4*)&us[j*128 + q*4];
        float4 vi = *(float4*)&vs[i*128 + q*4];
        float4 r;
        r.x = ui.x*vj.x - uj.x*vi.x;
        r.y = ui.y*vj.y - uj.y*vi.y;
        r.z = ui.z*vj.z - uj.z*vi.z;
        r.w = ui.w*vj.w - uj.w*vi.w;
        __stcs((float4*)(obase + (size_t)p*NPIX), r);
    }
}

// ---------------- launch ----------------
extern "C" void kernel_launch(void* const* d_in, const int* in_sizes, int n_in,
                              void* d_out, int out_size) {
    const float* f    = (const float*)d_in[0];   // [16,8,64,64]
    const float* kern = (const float*)d_in[1];   // [1,8,16,64,64]
    float* out = (float*)d_out;                  // [16,128,128,128]
    (void)in_sizes; (void)n_in; (void)out_size;

    cudaFuncSetAttribute(k_itrans, cudaFuncAttributeMaxDynamicSharedMemorySize, SM2_TOT);

    k_init   <<<40,   256>>>();
    k_fft64  <<<256,  512>>>(f, kern);
    k_conv   <<<2016, 256>>>();
    k_itrans <<<2560, 128, SM2_TOT>>>(out);
    k_cross  <<<2048, 128>>>(out);
}

// round 13
// speedup vs baseline: 1.1887x; 1.0294x over previous
#include <cuda_runtime.h>
#include <math.h>

// Problem constants
#define NBATCH 16
#define NC1 8
#define NC2 16
#define NM 63
#define NK2 32
#define NF (NM*NK2)  /* 2016 */
#define NPIX 16384   /* 128*128 */

// ---------------- device scratch ----------------
__device__ float2  g_Kf[128*NF];
__device__ float2  g_Ff[128*NF];
__device__ float2  g_Cf[256*NF];
__device__ float   g_u[256*NPIX];
__device__ float   g_v[256*NPIX];
__device__ float2  g_Ey[64*32];
__device__ float2  g_Ex[64*64];
__device__ float2  g_WxT[63*128];
__device__ float2  g_WyT[32*128];
__device__ float   g_MU[NF];
__device__ float   g_MV[NF];
__device__ int     g_I[120], g_J[120];

// ---------------- table init (parallel) ----------------
__global__ void k_init() {
    int tid = blockIdx.x*256 + threadIdx.x;
    int stride = gridDim.x*256;
    for (int idx = tid; idx < 64*32; idx += stride) {
        int y = idx >> 5, k2 = idx & 31;
        float s, c; sincospif(-2.0f * (float)(k2*y) / 64.0f, &s, &c);
        g_Ey[idx] = make_float2(c, s);
    }
    for (int idx = tid; idx < 64*64; idx += stride) {
        int m = idx >> 6, x = idx & 63; int k1 = m - 31;
        float s, c; sincospif(-2.0f * (float)(k1*x) / 64.0f, &s, &c);
        g_Ex[idx] = make_float2(c, s);
    }
    for (int idx = tid; idx < 63*128; idx += stride) {
        int m = idx >> 7, n1 = idx & 127; int k1 = m - 31;
        float s, c; sincospif(2.0f * (float)(k1*n1) / 128.0f, &s, &c);
        g_WxT[idx] = make_float2(c, s);
    }
    for (int idx = tid; idx < 32*128; idx += stride) {
        int k2 = idx >> 7, n2 = idx & 127;
        float s, c; sincospif(2.0f * (float)(k2*n2) / 128.0f, &s, &c);
        float sc = ((k2 == 0) ? 1.0f : 2.0f) * (2.0f / 16384.0f);
        g_WyT[idx] = make_float2(c * sc, s * sc);
    }
    for (int idx = tid; idx < NF; idx += stride) {
        int m = idx >> 5, k2 = idx & 31; int k1 = m - 31;
        float den = (float)(k1*k1 + k2*k2);
        if (den == 0.0f) den = 1.0f;
        g_MU[idx] =  (float)k2 / den;
        g_MV[idx] = -(float)k1 / den;
    }
    for (int p = tid; p < 120; p += stride) {
        int off = p, i = 0, cnt = 15;
        while (off >= cnt) { off -= cnt; i++; cnt--; }
        g_I[p] = i; g_J[p] = i + 1 + off;
    }
}

// ---------------- forward DFT (512 threads; fused D4 symmetrization) ----
__global__ void __launch_bounds__(512) k_fft64(const float* __restrict__ f,
                                               const float* __restrict__ kin) {
    __shared__ float  ss[4096];
    __shared__ float2 sA[2048];
    int ch = blockIdx.x;
    int t = threadIdx.x;
    bool isK = (ch < 128);
    const float* src = isK ? (kin + ch*4096) : (f + (ch-128)*4096);
    for (int i = t; i < 4096; i += 512) ss[i] = src[i];
    __syncthreads();
    if (isK) {
        float rv[8];
        #pragma unroll
        for (int r = 0; r < 8; r++) {
            int idx = t + 512*r;
            int a = idx >> 6, b = idx & 63;
            int na = (64 - a) & 63, nb = (64 - b) & 63;
            rv[r] = (ss[a*64 + b]  + ss[nb*64 + a] + ss[na*64 + nb] + ss[b*64 + na]
                   + ss[b*64 + a]  + ss[a*64 + nb] + ss[nb*64 + na] + ss[na*64 + b]) * 0.125f;
        }
        __syncthreads();
        #pragma unroll
        for (int r = 0; r < 8; r++) ss[t + 512*r] = rv[r];
        __syncthreads();
    }
    int k2 = t & 31, grp = t >> 5;
    {
        float2 acc[4];
        #pragma unroll
        for (int r = 0; r < 4; r++) acc[r] = make_float2(0.f, 0.f);
        for (int y = 0; y < 64; y++) {
            float2 e = g_Ey[y*32 + k2];
            #pragma unroll
            for (int r = 0; r < 4; r++) {
                float sv = ss[(grp*4 + r)*64 + y];
                acc[r].x = fmaf(sv, e.x, acc[r].x);
                acc[r].y = fmaf(sv, e.y, acc[r].y);
            }
        }
        #pragma unroll
        for (int r = 0; r < 4; r++) sA[(grp*4 + r)*32 + k2] = acc[r];
    }
    __syncthreads();
    {
        float2 acc[4];
        #pragma unroll
        for (int r = 0; r < 4; r++) acc[r] = make_float2(0.f, 0.f);
        for (int x = 0; x < 64; x++) {
            #pragma unroll
            for (int r = 0; r < 4; r++) {
                int m = grp*4 + r;
                float2 e = g_Ex[m*64 + x];
                float2 a = sA[x*32 + k2];
                acc[r].x = fmaf(e.x, a.x, fmaf(-e.y, a.y, acc[r].x));
                acc[r].y = fmaf(e.x, a.y, fmaf( e.y, a.x, acc[r].y));
            }
        }
        float2* dstF = isK ? (g_Kf + ch*NF) : (g_Ff + (ch-128)*NF);
        #pragma unroll
        for (int r = 0; r < 4; r++) {
            int m = grp*4 + r;
            if (m < 63) dstF[m*32 + k2] = acc[r];
        }
    }
}

// ---------------- channel contraction ----------------
__global__ void k_conv() {
    int idx = blockIdx.x * 256 + threadIdx.x;
    int mk = idx % NF;
    int bj = idx / NF;
    int b = bj >> 4, j = bj & 15;
    float2 acc = make_float2(0.f, 0.f);
    #pragma unroll
    for (int i = 0; i < 8; i++) {
        float2 Fv = g_Ff[(b*8 + i)*NF + mk];
        float2 Kv = g_Kf[(i*16 + j)*NF + mk];
        acc.x = fmaf(Fv.x, Kv.x, fmaf(-Fv.y, Kv.y, acc.x));
        acc.y = fmaf(Fv.x, Kv.y, fmaf( Fv.y, Kv.x, acc.y));
    }
    g_Cf[bj*NF + mk] = acc;
}

// ---------------- fused inverse transform: quarter-channel ------------------
// grid = 640 ch * 4 quarters, 128 threads, 5 CTA/SM.
// Stage1 AND stage2 twiddles via complex recurrence (no per-iter LDG).
#define SM2_SD   0
#define SM2_Z    15872
#define SM2_Q    16128
#define SM2_TOT  (16128 + 8704)

__global__ void __launch_bounds__(128, 5) k_itrans(float* __restrict__ out) {
    extern __shared__ char sm[];
    float4* SD = (float4*)(sm + SM2_SD);      // [(k1-1)*32 + k2]
    float2* Zs = (float2*)(sm + SM2_Z);
    float2* Qs = (float2*)(sm + SM2_Q);       // [k2*34 + j]

    int t = threadIdx.x;
    int ch = blockIdx.x >> 2, qt = blockIdx.x & 3;
    const float2* src; float* dst; const float* mul = nullptr; float msgn = 1.0f;
    if (ch < 128) {
        src = g_Ff + ch*NF;
        int b = ch >> 3, c = ch & 7;
        dst = out + (size_t)(b*128 + c) * NPIX;
    } else if (ch < 384) {
        int c2 = ch - 128; src = g_Cf + c2*NF; dst = g_u + (size_t)c2*NPIX; mul = g_MU;
    } else {
        int c2 = ch - 384; src = g_Cf + c2*NF; dst = g_v + (size_t)c2*NPIX; mul = g_MV; msgn = -1.0f;
    }

    // phase 1: build S/D from global
    for (int e = t; e < 992; e += 128) {
        int k1 = (e >> 5) + 1, k2 = e & 31;
        float2 gp = src[(31 + k1)*32 + k2];
        float2 gm = src[(31 - k1)*32 + k2];
        float2 a, b;
        if (mul) {
            float m = mul[(31 + k1)*32 + k2];
            a = make_float2(-m*gp.y, m*gp.x);
            float mm = msgn * m;
            b = make_float2(-mm*gm.y, mm*gm.x);
        } else {
            a = gp; b = gm;
        }
        SD[e] = make_float4(a.x + b.x, a.y + b.y, a.x - b.x, a.y - b.y);
    }
    if (t < 32) {
        float2 z = src[31*32 + t];
        if (mul) {
            float m = mul[31*32 + t];
            z = make_float2(-m*z.y, m*z.x);
        }
        Zs[t] = z;
    }
    __syncthreads();

    // phase 2a: Q[k2][n1=64] (qt==0 only)
    if (qt == 0 && t < 32) {
        float2 z = Zs[t];
        float pr = z.x, pi = z.y;
        #pragma unroll
        for (int k1 = 1; k1 < 32; k1++) {
            float4 sd = SD[(k1-1)*32 + t];
            float sgn = (k1 & 1) ? -1.0f : 1.0f;
            pr = fmaf(sgn, sd.x, pr);
            pi = fmaf(sgn, sd.y, pi);
        }
        Qs[t*34 + 32] = make_float2(pr, pi);
    }

    // phase 2b: stage1 — one n1h x 4 k2; w via recurrence, SD pipelined
    {
        int jl = t & 15, kg = t >> 4, k2b = kg*4;
        int n1 = qt*16 + jl;
        float P[4], R[4], T[4], U[4];
        #pragma unroll
        for (int u = 0; u < 4; u++) { P[u]=0.f; R[u]=0.f; T[u]=0.f; U[u]=0.f; }
        float2 step = g_WxT[32*128 + n1];   // e^{2*pi*i*n1/128}
        float2 w = step;
        float4 s0 = SD[k2b+0], s1 = SD[k2b+1], s2 = SD[k2b+2], s3 = SD[k2b+3];
        #pragma unroll
        for (int k1 = 1; k1 <= 31; k1++) {
            float4 c0 = s0, c1 = s1, c2 = s2, c3 = s3;
            float2 wc = w;
            if (k1 < 31) {
                const float4* p = SD + k1*32 + k2b;
                s0 = p[0]; s1 = p[1]; s2 = p[2]; s3 = p[3];
                float wx = fmaf(wc.x, step.x, -wc.y*step.y);
                float wy = fmaf(wc.x, step.y,  wc.y*step.x);
                w = make_float2(wx, wy);
            }
            P[0]=fmaf(wc.x,c0.x,P[0]); T[0]=fmaf(wc.x,c0.y,T[0]); U[0]=fmaf(wc.y,c0.z,U[0]); R[0]=fmaf(wc.y,c0.w,R[0]);
            P[1]=fmaf(wc.x,c1.x,P[1]); T[1]=fmaf(wc.x,c1.y,T[1]); U[1]=fmaf(wc.y,c1.z,U[1]); R[1]=fmaf(wc.y,c1.w,R[1]);
            P[2]=fmaf(wc.x,c2.x,P[2]); T[2]=fmaf(wc.x,c2.y,T[2]); U[2]=fmaf(wc.y,c2.z,U[2]); R[2]=fmaf(wc.y,c2.w,R[2]);
            P[3]=fmaf(wc.x,c3.x,P[3]); T[3]=fmaf(wc.x,c3.y,T[3]); U[3]=fmaf(wc.y,c3.z,U[3]); R[3]=fmaf(wc.y,c3.w,R[3]);
        }
        #pragma unroll
        for (int u = 0; u < 4; u++) {
            int k2 = k2b + u;
            float2 z = Zs[k2];
            Qs[k2*34 + jl]      = make_float2(z.x + P[u] - R[u], z.y + T[u] + U[u]);
            Qs[k2*34 + 16 + jl] = make_float2(z.x + P[u] + R[u], z.y + T[u] - U[u]);
        }
    }
    __syncthreads();

    // phase 3a: n2 = 64 column
    if (t < 32) {
        int j = t;
        int n1row = (j < 16) ? (qt*16 + j) : ((128 - (qt*16 + j - 16)) & 127);
        float acc = 0.f;
        #pragma unroll
        for (int k2 = 0; k2 < 32; k2++)
            acc = fmaf(g_WyT[k2*128 + 64].x, Qs[k2*34 + j].x, acc);
        dst[n1row*128 + 64] = acc;
    } else if (qt == 0 && t == 32) {
        float acc = 0.f;
        #pragma unroll
        for (int k2 = 0; k2 < 32; k2++)
            acc = fmaf(g_WyT[k2*128 + 64].x, Qs[k2*34 + 32].x, acc);
        dst[64*128 + 64] = acc;
    }

    // phase 3b: stage2 — Wy via 4 phase recurrences; pure LDS+FMA inner loop.
    //   A[u][j] = qr0[u]/2 + sum_{k2>=1} qr(k2,u) * px(k2,j)
    //   B[u][j] =            sum_{k2>=1} qi(k2,u) * py(k2,j)
    //   out_fwd = s*(A-B), out_mir = s*(A+B),  s = 1/4096
    {
        int tx = t & 15, ty = t >> 4;
        int jb = ty*4;
        const float S = 1.0f/4096.0f;
        float A[4][4], B[4][4];
        // k2 = 0 term
        {
            float4 q01 = *(const float4*)&Qs[jb];
            float4 q23 = *(const float4*)&Qs[jb + 2];
            float h0 = 0.5f*q01.x, h1 = 0.5f*q01.z, h2 = 0.5f*q23.x, h3 = 0.5f*q23.z;
            #pragma unroll
            for (int j = 0; j < 4; j++) {
                A[0][j] = h0; A[1][j] = h1; A[2][j] = h2; A[3][j] = h3;
                B[0][j] = 0.f; B[1][j] = 0.f; B[2][j] = 0.f; B[3][j] = 0.f;
            }
        }
        // phase steps: e^{2*pi*i*(tx*4+j)/128} from WxT row k1=+1
        float2 st0 = g_WxT[32*128 + tx*4 + 0];
        float2 st1 = g_WxT[32*128 + tx*4 + 1];
        float2 st2 = g_WxT[32*128 + tx*4 + 2];
        float2 st3 = g_WxT[32*128 + tx*4 + 3];
        float2 p0 = st0, p1 = st1, p2 = st2, p3 = st3;
        float4 q01 = *(const float4*)&Qs[34 + jb];
        float4 q23 = *(const float4*)&Qs[34 + jb + 2];
        #pragma unroll
        for (int k2 = 1; k2 <= 31; k2++) {
            float4 qc01 = q01, qc23 = q23;
            float2 c0 = p0, c1 = p1, c2 = p2, c3 = p3;
            if (k2 < 31) {
                q01 = *(const float4*)&Qs[(k2+1)*34 + jb];
                q23 = *(const float4*)&Qs[(k2+1)*34 + jb + 2];
                p0 = make_float2(fmaf(c0.x,st0.x,-c0.y*st0.y), fmaf(c0.x,st0.y, c0.y*st0.x));
                p1 = make_float2(fmaf(c1.x,st1.x,-c1.y*st1.y), fmaf(c1.x,st1.y, c1.y*st1.x));
                p2 = make_float2(fmaf(c2.x,st2.x,-c2.y*st2.y), fmaf(c2.x,st2.y, c2.y*st2.x));
                p3 = make_float2(fmaf(c3.x,st3.x,-c3.y*st3.y), fmaf(c3.x,st3.y, c3.y*st3.x));
            }
            A[0][0]=fmaf(qc01.x,c0.x,A[0][0]); B[0][0]=fmaf(qc01.y,c0.y,B[0][0]);
            A[0][1]=fmaf(qc01.x,c1.x,A[0][1]); B[0][1]=fmaf(qc01.y,c1.y,B[0][1]);
            A[0][2]=fmaf(qc01.x,c2.x,A[0][2]); B[0][2]=fmaf(qc01.y,c2.y,B[0][2]);
            A[0][3]=fmaf(qc01.x,c3.x,A[0][3]); B[0][3]=fmaf(qc01.y,c3.y,B[0][3]);
            A[1][0]=fmaf(qc01.z,c0.x,A[1][0]); B[1][0]=fmaf(qc01.w,c0.y,B[1][0]);
            A[1][1]=fmaf(qc01.z,c1.x,A[1][1]); B[1][1]=fmaf(qc01.w,c1.y,B[1][1]);
            A[1][2]=fmaf(qc01.z,c2.x,A[1][2]); B[1][2]=fmaf(qc01.w,c2.y,B[1][2]);
            A[1][3]=fmaf(qc01.z,c3.x,A[1][3]); B[1][3]=fmaf(qc01.w,c3.y,B[1][3]);
            A[2][0]=fmaf(qc23.x,c0.x,A[2][0]); B[2][0]=fmaf(qc23.y,c0.y,B[2][0]);
            A[2][1]=fmaf(qc23.x,c1.x,A[2][1]); B[2][1]=fmaf(qc23.y,c1.y,B[2][1]);
            A[2][2]=fmaf(qc23.x,c2.x,A[2][2]); B[2][2]=fmaf(qc23.y,c2.y,B[2][2]);
            A[2][3]=fmaf(qc23.x,c3.x,A[2][3]); B[2][3]=fmaf(qc23.y,c3.y,B[2][3]);
            A[3][0]=fmaf(qc23.z,c0.x,A[3][0]); B[3][0]=fmaf(qc23.w,c0.y,B[3][0]);
            A[3][1]=fmaf(qc23.z,c1.x,A[3][1]); B[3][1]=fmaf(qc23.w,c1.y,B[3][1]);
            A[3][2]=fmaf(qc23.z,c2.x,A[3][2]); B[3][2]=fmaf(qc23.w,c2.y,B[3][2]);
            A[3][3]=fmaf(qc23.z,c3.x,A[3][3]); B[3][3]=fmaf(qc23.w,c3.y,B[3][3]);
        }
        #pragma unroll
        for (int u = 0; u < 4; u++) {
            int j = jb + u;
            int n1row = (j < 16) ? (qt*16 + j) : ((128 - (qt*16 + j - 16)) & 127);
            float* row = dst + n1row*128;
            *(float4*)(row + tx*4) = make_float4(S*(A[u][0]-B[u][0]), S*(A[u][1]-B[u][1]),
                                                 S*(A[u][2]-B[u][2]), S*(A[u][3]-B[u][3]));
            #pragma unroll
            for (int jj = 0; jj < 4; jj++)
                row[(128 - (tx*4 + jj)) & 127] = S*(A[u][jj]+B[u][jj]);
        }
    }

    // phase 3c: output row n1 = 64 (qt==0 only)
    if (qt == 0) {
        int n2 = t;
        float acc = 0.f;
        #pragma unroll 4
        for (int k2 = 0; k2 < 32; k2++) {
            float2 q = Qs[k2*34 + 32];
            float2 w = g_WyT[k2*128 + n2];
            acc = fmaf(q.x, w.x, fmaf(-q.y, w.y, acc));
        }
        if (n2 != 64) dst[64*128 + n2] = acc;
    }
}

// ---------------- cross products (streaming stores) ----------------
__global__ void __launch_bounds__(128) k_cross(float* __restrict__ out) {
    __shared__ float us[16*128], vs[16*128];
    int b = blockIdx.x >> 7, n1 = blockIdx.x & 127;
    int t = threadIdx.x;
    for (int i = t; i < 16*128; i += 128) {
        int c = i >> 7, n2 = i & 127;
        us[i] = g_u[((size_t)(b*16 + c)*128 + n1)*128 + n2];
        vs[i] = g_v[((size_t)(b*16 + c)*128 + n1)*128 + n2];
    }
    __syncthreads();
    int q = t & 31, g = t >> 5;
    float* obase = out + ((size_t)b*128 + 8)*NPIX + n1*128 + q*4;
    #pragma unroll 2
    for (int pp = 0; pp < 30; pp++) {
        int p = g*30 + pp;
        int i = g_I[p], j = g_J[p];
        float4 ui = *(float4*)&us[i*128 + q*4];
        float4 vj = *(float4*)&vs[j*128 + q*4];
        float4 uj = *(float4*)&us[j*128 + q*4];
        float4 vi = *(float4*)&vs[i*128 + q*4];
        float4 r;
        r.x = ui.x*vj.x - uj.x*vi.x;
        r.y = ui.y*vj.y - uj.y*vi.y;
        r.z = ui.z*vj.z - uj.z*vi.z;
        r.w = ui.w*vj.w - uj.w*vi.w;
        __stcs((float4*)(obase + (size_t)p*NPIX), r);
    }
}

// ---------------- launch ----------------
extern "C" void kernel_launch(void* const* d_in, const int* in_sizes, int n_in,
                              void* d_out, int out_size) {
    const float* f    = (const float*)d_in[0];   // [16,8,64,64]
    const float* kern = (const float*)d_in[1];   // [1,8,16,64,64]
    float* out = (float*)d_out;                  // [16,128,128,128]
    (void)in_sizes; (void)n_in; (void)out_size;

    cudaFuncSetAttribute(k_itrans, cudaFuncAttributeMaxDynamicSharedMemorySize, SM2_TOT);

    k_init   <<<40,   256>>>();
    k_fft64  <<<256,  512>>>(f, kern);
    k_conv   <<<2016, 256>>>();
    k_itrans <<<2560, 128, SM2_TOT>>>(out);
    k_cross  <<<2048, 128>>>(out);
}

// round 14
// speedup vs baseline: 1.2133x; 1.0207x over previous
#include <cuda_runtime.h>
#include <math.h>

// Problem constants
#define NBATCH 16
#define NC1 8
#define NC2 16
#define NM 63
#define NK2 32
#define NF (NM*NK2)  /* 2016 */
#define NPIX 16384   /* 128*128 */

// ---------------- device scratch ----------------
__device__ float2  g_Kf[128*NF];
__device__ float2  g_Ff[128*NF];
__device__ float2  g_Cf[256*NF];
__device__ float   g_u[256*NPIX];
__device__ float   g_v[256*NPIX];
__device__ float2  g_Ey[64*32];
__device__ float2  g_Ex[64*64];
__device__ float2  g_WxT[63*128];
__device__ float2  g_WyT[32*128];
__device__ float   g_MU[NF];
__device__ float   g_MV[NF];
__device__ int     g_I[120], g_J[120];

// ---------------- table init (parallel) ----------------
__global__ void k_init() {
    int tid = blockIdx.x*256 + threadIdx.x;
    int stride = gridDim.x*256;
    for (int idx = tid; idx < 64*32; idx += stride) {
        int y = idx >> 5, k2 = idx & 31;
        float s, c; sincospif(-2.0f * (float)(k2*y) / 64.0f, &s, &c);
        g_Ey[idx] = make_float2(c, s);
    }
    for (int idx = tid; idx < 64*64; idx += stride) {
        int m = idx >> 6, x = idx & 63; int k1 = m - 31;
        float s, c; sincospif(-2.0f * (float)(k1*x) / 64.0f, &s, &c);
        g_Ex[idx] = make_float2(c, s);
    }
    for (int idx = tid; idx < 63*128; idx += stride) {
        int m = idx >> 7, n1 = idx & 127; int k1 = m - 31;
        float s, c; sincospif(2.0f * (float)(k1*n1) / 128.0f, &s, &c);
        g_WxT[idx] = make_float2(c, s);
    }
    for (int idx = tid; idx < 32*128; idx += stride) {
        int k2 = idx >> 7, n2 = idx & 127;
        float s, c; sincospif(2.0f * (float)(k2*n2) / 128.0f, &s, &c);
        float sc = ((k2 == 0) ? 1.0f : 2.0f) * (2.0f / 16384.0f);
        g_WyT[idx] = make_float2(c * sc, s * sc);
    }
    for (int idx = tid; idx < NF; idx += stride) {
        int m = idx >> 5, k2 = idx & 31; int k1 = m - 31;
        float den = (float)(k1*k1 + k2*k2);
        if (den == 0.0f) den = 1.0f;
        g_MU[idx] =  (float)k2 / den;
        g_MV[idx] = -(float)k1 / den;
    }
    for (int p = tid; p < 120; p += stride) {
        int off = p, i = 0, cnt = 15;
        while (off >= cnt) { off -= cnt; i++; cnt--; }
        g_I[p] = i; g_J[p] = i + 1 + off;
    }
}

// ---------------- forward DFT (512 threads; fused D4 symmetrization) ----
__global__ void __launch_bounds__(512) k_fft64(const float* __restrict__ f,
                                               const float* __restrict__ kin) {
    __shared__ float  ss[4096];
    __shared__ float2 sA[2048];
    int ch = blockIdx.x;
    int t = threadIdx.x;
    bool isK = (ch < 128);
    const float* src = isK ? (kin + ch*4096) : (f + (ch-128)*4096);
    for (int i = t; i < 4096; i += 512) ss[i] = src[i];
    __syncthreads();
    if (isK) {
        float rv[8];
        #pragma unroll
        for (int r = 0; r < 8; r++) {
            int idx = t + 512*r;
            int a = idx >> 6, b = idx & 63;
            int na = (64 - a) & 63, nb = (64 - b) & 63;
            rv[r] = (ss[a*64 + b]  + ss[nb*64 + a] + ss[na*64 + nb] + ss[b*64 + na]
                   + ss[b*64 + a]  + ss[a*64 + nb] + ss[nb*64 + na] + ss[na*64 + b]) * 0.125f;
        }
        __syncthreads();
        #pragma unroll
        for (int r = 0; r < 8; r++) ss[t + 512*r] = rv[r];
        __syncthreads();
    }
    int k2 = t & 31, grp = t >> 5;
    {
        float2 acc[4];
        #pragma unroll
        for (int r = 0; r < 4; r++) acc[r] = make_float2(0.f, 0.f);
        for (int y = 0; y < 64; y++) {
            float2 e = g_Ey[y*32 + k2];
            #pragma unroll
            for (int r = 0; r < 4; r++) {
                float sv = ss[(grp*4 + r)*64 + y];
                acc[r].x = fmaf(sv, e.x, acc[r].x);
                acc[r].y = fmaf(sv, e.y, acc[r].y);
            }
        }
        #pragma unroll
        for (int r = 0; r < 4; r++) sA[(grp*4 + r)*32 + k2] = acc[r];
    }
    __syncthreads();
    {
        float2 acc[4];
        #pragma unroll
        for (int r = 0; r < 4; r++) acc[r] = make_float2(0.f, 0.f);
        for (int x = 0; x < 64; x++) {
            #pragma unroll
            for (int r = 0; r < 4; r++) {
                int m = grp*4 + r;
                float2 e = g_Ex[m*64 + x];
                float2 a = sA[x*32 + k2];
                acc[r].x = fmaf(e.x, a.x, fmaf(-e.y, a.y, acc[r].x));
                acc[r].y = fmaf(e.x, a.y, fmaf( e.y, a.x, acc[r].y));
            }
        }
        float2* dstF = isK ? (g_Kf + ch*NF) : (g_Ff + (ch-128)*NF);
        #pragma unroll
        for (int r = 0; r < 4; r++) {
            int m = grp*4 + r;
            if (m < 63) dstF[m*32 + k2] = acc[r];
        }
    }
}

// ---------------- channel contraction (float4 vectorized) ----------------
// 2 frequency points per thread. 256 bj * 1008 quad-elems = 258048 threads.
__global__ void k_conv() {
    int idx = blockIdx.x * 256 + threadIdx.x;       // 0 .. 258047
    int mk2 = idx % 1008;                           // pair index
    int bj  = idx / 1008;
    int b = bj >> 4, j = bj & 15;
    float4 acc = make_float4(0.f, 0.f, 0.f, 0.f);
    #pragma unroll
    for (int i = 0; i < 8; i++) {
        float4 Fv = *(const float4*)&g_Ff[(b*8 + i)*NF + mk2*2];
        float4 Kv = *(const float4*)&g_Kf[(i*16 + j)*NF + mk2*2];
        acc.x = fmaf(Fv.x, Kv.x, fmaf(-Fv.y, Kv.y, acc.x));
        acc.y = fmaf(Fv.x, Kv.y, fmaf( Fv.y, Kv.x, acc.y));
        acc.z = fmaf(Fv.z, Kv.z, fmaf(-Fv.w, Kv.w, acc.z));
        acc.w = fmaf(Fv.z, Kv.w, fmaf( Fv.w, Kv.z, acc.w));
    }
    *(float4*)&g_Cf[bj*NF + mk2*2] = acc;
}

// ---------------- fused inverse transform: 2 quarters/block ----------------
// grid = 640 ch * 2 halves; block loops qt = qh*2 + {0,1}. SD built ONCE.
#define SM2_SD   0
#define SM2_Z    15872
#define SM2_Q    16128
#define SM2_TOT  (16128 + 8704)

__global__ void __launch_bounds__(128, 5) k_itrans(float* __restrict__ out) {
    extern __shared__ char sm[];
    float4* SD = (float4*)(sm + SM2_SD);      // [(k1-1)*32 + k2]
    float2* Zs = (float2*)(sm + SM2_Z);
    float2* Qs = (float2*)(sm + SM2_Q);       // [k2*34 + j]

    int t = threadIdx.x;
    int ch = blockIdx.x >> 1, qh = blockIdx.x & 1;
    const float2* src; float* dst; const float* mul = nullptr; float msgn = 1.0f;
    if (ch < 128) {
        src = g_Ff + ch*NF;
        int b = ch >> 3, c = ch & 7;
        dst = out + (size_t)(b*128 + c) * NPIX;
    } else if (ch < 384) {
        int c2 = ch - 128; src = g_Cf + c2*NF; dst = g_u + (size_t)c2*NPIX; mul = g_MU;
    } else {
        int c2 = ch - 384; src = g_Cf + c2*NF; dst = g_v + (size_t)c2*NPIX; mul = g_MV; msgn = -1.0f;
    }

    // phase 1: build S/D from global (once per block)
    for (int e = t; e < 992; e += 128) {
        int k1 = (e >> 5) + 1, k2 = e & 31;
        float2 gp = src[(31 + k1)*32 + k2];
        float2 gm = src[(31 - k1)*32 + k2];
        float2 a, b;
        if (mul) {
            float m = mul[(31 + k1)*32 + k2];
            a = make_float2(-m*gp.y, m*gp.x);
            float mm = msgn * m;
            b = make_float2(-mm*gm.y, mm*gm.x);
        } else {
            a = gp; b = gm;
        }
        SD[e] = make_float4(a.x + b.x, a.y + b.y, a.x - b.x, a.y - b.y);
    }
    if (t < 32) {
        float2 z = src[31*32 + t];
        if (mul) {
            float m = mul[31*32 + t];
            z = make_float2(-m*z.y, m*z.x);
        }
        Zs[t] = z;
    }
    __syncthreads();

    #pragma unroll 1
    for (int qi = 0; qi < 2; qi++) {
        int qt = qh*2 + qi;

        // phase 2a: Q[k2][n1=64] (qt==0 only)
        if (qt == 0 && t < 32) {
            float2 z = Zs[t];
            float pr = z.x, pi = z.y;
            #pragma unroll
            for (int k1 = 1; k1 < 32; k1++) {
                float4 sd = SD[(k1-1)*32 + t];
                float sgn = (k1 & 1) ? -1.0f : 1.0f;
                pr = fmaf(sgn, sd.x, pr);
                pi = fmaf(sgn, sd.y, pi);
            }
            Qs[t*34 + 32] = make_float2(pr, pi);
        }

        // phase 2b: stage1 — one n1h x 4 k2; w via recurrence, SD pipelined
        {
            int jl = t & 15, kg = t >> 4, k2b = kg*4;
            int n1 = qt*16 + jl;
            float P[4], R[4], T[4], U[4];
            #pragma unroll
            for (int u = 0; u < 4; u++) { P[u]=0.f; R[u]=0.f; T[u]=0.f; U[u]=0.f; }
            float2 step = g_WxT[32*128 + n1];
            float2 w = step;
            float4 s0 = SD[k2b+0], s1 = SD[k2b+1], s2 = SD[k2b+2], s3 = SD[k2b+3];
            #pragma unroll
            for (int k1 = 1; k1 <= 31; k1++) {
                float4 c0 = s0, c1 = s1, c2 = s2, c3 = s3;
                float2 wc = w;
                if (k1 < 31) {
                    const float4* p = SD + k1*32 + k2b;
                    s0 = p[0]; s1 = p[1]; s2 = p[2]; s3 = p[3];
                    float wx = fmaf(wc.x, step.x, -wc.y*step.y);
                    float wy = fmaf(wc.x, step.y,  wc.y*step.x);
                    w = make_float2(wx, wy);
                }
                P[0]=fmaf(wc.x,c0.x,P[0]); T[0]=fmaf(wc.x,c0.y,T[0]); U[0]=fmaf(wc.y,c0.z,U[0]); R[0]=fmaf(wc.y,c0.w,R[0]);
                P[1]=fmaf(wc.x,c1.x,P[1]); T[1]=fmaf(wc.x,c1.y,T[1]); U[1]=fmaf(wc.y,c1.z,U[1]); R[1]=fmaf(wc.y,c1.w,R[1]);
                P[2]=fmaf(wc.x,c2.x,P[2]); T[2]=fmaf(wc.x,c2.y,T[2]); U[2]=fmaf(wc.y,c2.z,U[2]); R[2]=fmaf(wc.y,c2.w,R[2]);
                P[3]=fmaf(wc.x,c3.x,P[3]); T[3]=fmaf(wc.x,c3.y,T[3]); U[3]=fmaf(wc.y,c3.z,U[3]); R[3]=fmaf(wc.y,c3.w,R[3]);
            }
            #pragma unroll
            for (int u = 0; u < 4; u++) {
                int k2 = k2b + u;
                float2 z = Zs[k2];
                Qs[k2*34 + jl]      = make_float2(z.x + P[u] - R[u], z.y + T[u] + U[u]);
                Qs[k2*34 + 16 + jl] = make_float2(z.x + P[u] + R[u], z.y + T[u] - U[u]);
            }
        }
        __syncthreads();

        // phase 3a: n2 = 64 column
        if (t < 32) {
            int j = t;
            int n1row = (j < 16) ? (qt*16 + j) : ((128 - (qt*16 + j - 16)) & 127);
            float acc = 0.f;
            #pragma unroll
            for (int k2 = 0; k2 < 32; k2++)
                acc = fmaf(g_WyT[k2*128 + 64].x, Qs[k2*34 + j].x, acc);
            dst[n1row*128 + 64] = acc;
        } else if (qt == 0 && t == 32) {
            float acc = 0.f;
            #pragma unroll
            for (int k2 = 0; k2 < 32; k2++)
                acc = fmaf(g_WyT[k2*128 + 64].x, Qs[k2*34 + 32].x, acc);
            dst[64*128 + 64] = acc;
        }

        // phase 3b: stage2 — Wy via 4 phase recurrences; pure LDS+FMA loop
        {
            int tx = t & 15, ty = t >> 4;
            int jb = ty*4;
            const float S = 1.0f/4096.0f;
            float A[4][4], B[4][4];
            {
                float4 q01 = *(const float4*)&Qs[jb];
                float4 q23 = *(const float4*)&Qs[jb + 2];
                float h0 = 0.5f*q01.x, h1 = 0.5f*q01.z, h2 = 0.5f*q23.x, h3 = 0.5f*q23.z;
                #pragma unroll
                for (int j = 0; j < 4; j++) {
                    A[0][j] = h0; A[1][j] = h1; A[2][j] = h2; A[3][j] = h3;
                    B[0][j] = 0.f; B[1][j] = 0.f; B[2][j] = 0.f; B[3][j] = 0.f;
                }
            }
            float2 st0 = g_WxT[32*128 + tx*4 + 0];
            float2 st1 = g_WxT[32*128 + tx*4 + 1];
            float2 st2 = g_WxT[32*128 + tx*4 + 2];
            float2 st3 = g_WxT[32*128 + tx*4 + 3];
            float2 p0 = st0, p1 = st1, p2 = st2, p3 = st3;
            float4 q01 = *(const float4*)&Qs[34 + jb];
            float4 q23 = *(const float4*)&Qs[34 + jb + 2];
            #pragma unroll
            for (int k2 = 1; k2 <= 31; k2++) {
                float4 qc01 = q01, qc23 = q23;
                float2 c0 = p0, c1 = p1, c2 = p2, c3 = p3;
                if (k2 < 31) {
                    q01 = *(const float4*)&Qs[(k2+1)*34 + jb];
                    q23 = *(const float4*)&Qs[(k2+1)*34 + jb + 2];
                    p0 = make_float2(fmaf(c0.x,st0.x,-c0.y*st0.y), fmaf(c0.x,st0.y, c0.y*st0.x));
                    p1 = make_float2(fmaf(c1.x,st1.x,-c1.y*st1.y), fmaf(c1.x,st1.y, c1.y*st1.x));
                    p2 = make_float2(fmaf(c2.x,st2.x,-c2.y*st2.y), fmaf(c2.x,st2.y, c2.y*st2.x));
                    p3 = make_float2(fmaf(c3.x,st3.x,-c3.y*st3.y), fmaf(c3.x,st3.y, c3.y*st3.x));
                }
                A[0][0]=fmaf(qc01.x,c0.x,A[0][0]); B[0][0]=fmaf(qc01.y,c0.y,B[0][0]);
                A[0][1]=fmaf(qc01.x,c1.x,A[0][1]); B[0][1]=fmaf(qc01.y,c1.y,B[0][1]);
                A[0][2]=fmaf(qc01.x,c2.x,A[0][2]); B[0][2]=fmaf(qc01.y,c2.y,B[0][2]);
                A[0][3]=fmaf(qc01.x,c3.x,A[0][3]); B[0][3]=fmaf(qc01.y,c3.y,B[0][3]);
                A[1][0]=fmaf(qc01.z,c0.x,A[1][0]); B[1][0]=fmaf(qc01.w,c0.y,B[1][0]);
                A[1][1]=fmaf(qc01.z,c1.x,A[1][1]); B[1][1]=fmaf(qc01.w,c1.y,B[1][1]);
                A[1][2]=fmaf(qc01.z,c2.x,A[1][2]); B[1][2]=fmaf(qc01.w,c2.y,B[1][2]);
                A[1][3]=fmaf(qc01.z,c3.x,A[1][3]); B[1][3]=fmaf(qc01.w,c3.y,B[1][3]);
                A[2][0]=fmaf(qc23.x,c0.x,A[2][0]); B[2][0]=fmaf(qc23.y,c0.y,B[2][0]);
                A[2][1]=fmaf(qc23.x,c1.x,A[2][1]); B[2][1]=fmaf(qc23.y,c1.y,B[2][1]);
                A[2][2]=fmaf(qc23.x,c2.x,A[2][2]); B[2][2]=fmaf(qc23.y,c2.y,B[2][2]);
                A[2][3]=fmaf(qc23.x,c3.x,A[2][3]); B[2][3]=fmaf(qc23.y,c3.y,B[2][3]);
                A[3][0]=fmaf(qc23.z,c0.x,A[3][0]); B[3][0]=fmaf(qc23.w,c0.y,B[3][0]);
                A[3][1]=fmaf(qc23.z,c1.x,A[3][1]); B[3][1]=fmaf(qc23.w,c1.y,B[3][1]);
                A[3][2]=fmaf(qc23.z,c2.x,A[3][2]); B[3][2]=fmaf(qc23.w,c2.y,B[3][2]);
                A[3][3]=fmaf(qc23.z,c3.x,A[3][3]); B[3][3]=fmaf(qc23.w,c3.y,B[3][3]);
            }
            #pragma unroll
            for (int u = 0; u < 4; u++) {
                int j = jb + u;
                int n1row = (j < 16) ? (qt*16 + j) : ((128 - (qt*16 + j - 16)) & 127);
                float* row = dst + n1row*128;
                *(float4*)(row + tx*4) = make_float4(S*(A[u][0]-B[u][0]), S*(A[u][1]-B[u][1]),
                                                     S*(A[u][2]-B[u][2]), S*(A[u][3]-B[u][3]));
                #pragma unroll
                for (int jj = 0; jj < 4; jj++)
                    row[(128 - (tx*4 + jj)) & 127] = S*(A[u][jj]+B[u][jj]);
            }
        }

        // phase 3c: output row n1 = 64 (qt==0 only)
        if (qt == 0) {
            int n2 = t;
            float acc = 0.f;
            #pragma unroll 4
            for (int k2 = 0; k2 < 32; k2++) {
                float2 q = Qs[k2*34 + 32];
                float2 w = g_WyT[k2*128 + n2];
                acc = fmaf(q.x, w.x, fmaf(-q.y, w.y, acc));
            }
            if (n2 != 64) dst[64*128 + n2] = acc;
        }
        __syncthreads();   // protect Qs reuse for next quarter
    }
}

// ---------------- cross products (streaming stores) ----------------
__global__ void __launch_bounds__(128) k_cross(float* __restrict__ out) {
    __shared__ float us[16*128], vs[16*128];
    int b = blockIdx.x >> 7, n1 = blockIdx.x & 127;
    int t = threadIdx.x;
    for (int i = t; i < 16*128; i += 128) {
        int c = i >> 7, n2 = i & 127;
        us[i] = g_u[((size_t)(b*16 + c)*128 + n1)*128 + n2];
        vs[i] = g_v[((size_t)(b*16 + c)*128 + n1)*128 + n2];
    }
    __syncthreads();
    int q = t & 31, g = t >> 5;
    float* obase = out + ((size_t)b*128 + 8)*NPIX + n1*128 + q*4;
    #pragma unroll 2
    for (int pp = 0; pp < 30; pp++) {
        int p = g*30 + pp;
        int i = g_I[p], j = g_J[p];
        float4 ui = *(float4*)&us[i*128 + q*4];
        float4 vj = *(float4*)&vs[j*128 + q*4];
        float4 uj = *(float4*)&us[j*128 + q*4];
        float4 vi = *(float4*)&vs[i*128 + q*4];
        float4 r;
        r.x = ui.x*vj.x - uj.x*vi.x;
        r.y = ui.y*vj.y - uj.y*vi.y;
        r.z = ui.z*vj.z - uj.z*vi.z;
        r.w = ui.w*vj.w - uj.w*vi.w;
        __stcs((float4*)(obase + (size_t)p*NPIX), r);
    }
}

// ---------------- launch ----------------
extern "C" void kernel_launch(void* const* d_in, const int* in_sizes, int n_in,
                              void* d_out, int out_size) {
    const float* f    = (const float*)d_in[0];   // [16,8,64,64]
    const float* kern = (const float*)d_in[1];   // [1,8,16,64,64]
    float* out = (float*)d_out;                  // [16,128,128,128]
    (void)in_sizes; (void)n_in; (void)out_size;

    cudaFuncSetAttribute(k_itrans, cudaFuncAttributeMaxDynamicSharedMemorySize, SM2_TOT);

    k_init   <<<40,   256>>>();
    k_fft64  <<<256,  512>>>(f, kern);
    k_conv   <<<1008, 256>>>();
    k_itrans <<<1280, 128, SM2_TOT>>>(out);
    k_cross  <<<2048, 128>>>(out);
}

// round 15
// speedup vs baseline: 1.2585x; 1.0373x over previous
#include <cuda_runtime.h>
#include <math.h>

// Problem constants
#define NBATCH 16
#define NC1 8
#define NC2 16
#define NM 63
#define NK2 32
#define NF (NM*NK2)  /* 2016 */
#define NPIX 16384   /* 128*128 */

typedef unsigned long long u64;

// ---- packed f32x2 helpers (sm_100+) ----
__device__ __forceinline__ u64 pk2(float lo, float hi) {
    u64 r;
    asm("mov.b64 %0, {%1, %2};" : "=l"(r) : "r"(__float_as_uint(lo)), "r"(__float_as_uint(hi)));
    return r;
}
__device__ __forceinline__ void upk2(u64 v, float& lo, float& hi) {
    unsigned a, b;
    asm("mov.b64 {%0, %1}, %2;" : "=r"(a), "=r"(b) : "l"(v));
    lo = __uint_as_float(a); hi = __uint_as_float(b);
}
__device__ __forceinline__ u64 fma2(u64 a, u64 b, u64 c) {
    u64 d; asm("fma.rn.f32x2 %0, %1, %2, %3;" : "=l"(d) : "l"(a), "l"(b), "l"(c)); return d;
}
__device__ __forceinline__ u64 mul2(u64 a, u64 b) {
    u64 d; asm("mul.rn.f32x2 %0, %1, %2;" : "=l"(d) : "l"(a), "l"(b)); return d;
}

// ---------------- device scratch ----------------
__device__ float2  g_Kf[128*NF];
__device__ float2  g_Ff[128*NF];
__device__ float2  g_Cf[256*NF];
__device__ float   g_u[256*NPIX];
__device__ float   g_v[256*NPIX];
__device__ float2  g_Ey[64*32];
__device__ float2  g_Ex[64*64];
__device__ float2  g_WxT[63*128];
__device__ float2  g_WyT[32*128];
__device__ float   g_MU[NF];
__device__ float   g_MV[NF];
__device__ int     g_I[120], g_J[120];

// ---------------- table init (parallel) ----------------
__global__ void k_init() {
    int tid = blockIdx.x*256 + threadIdx.x;
    int stride = gridDim.x*256;
    for (int idx = tid; idx < 64*32; idx += stride) {
        int y = idx >> 5, k2 = idx & 31;
        float s, c; sincospif(-2.0f * (float)(k2*y) / 64.0f, &s, &c);
        g_Ey[idx] = make_float2(c, s);
    }
    for (int idx = tid; idx < 64*64; idx += stride) {
        int m = idx >> 6, x = idx & 63; int k1 = m - 31;
        float s, c; sincospif(-2.0f * (float)(k1*x) / 64.0f, &s, &c);
        g_Ex[idx] = make_float2(c, s);
    }
    for (int idx = tid; idx < 63*128; idx += stride) {
        int m = idx >> 7, n1 = idx & 127; int k1 = m - 31;
        float s, c; sincospif(2.0f * (float)(k1*n1) / 128.0f, &s, &c);
        g_WxT[idx] = make_float2(c, s);
    }
    for (int idx = tid; idx < 32*128; idx += stride) {
        int k2 = idx >> 7, n2 = idx & 127;
        float s, c; sincospif(2.0f * (float)(k2*n2) / 128.0f, &s, &c);
        float sc = ((k2 == 0) ? 1.0f : 2.0f) * (2.0f / 16384.0f);
        g_WyT[idx] = make_float2(c * sc, s * sc);
    }
    for (int idx = tid; idx < NF; idx += stride) {
        int m = idx >> 5, k2 = idx & 31; int k1 = m - 31;
        float den = (float)(k1*k1 + k2*k2);
        if (den == 0.0f) den = 1.0f;
        g_MU[idx] =  (float)k2 / den;
        g_MV[idx] = -(float)k1 / den;
    }
    for (int p = tid; p < 120; p += stride) {
        int off = p, i = 0, cnt = 15;
        while (off >= cnt) { off -= cnt; i++; cnt--; }
        g_I[p] = i; g_J[p] = i + 1 + off;
    }
}

// ---------------- forward DFT (512 threads; fused D4 symmetrization) ----
__global__ void __launch_bounds__(512) k_fft64(const float* __restrict__ f,
                                               const float* __restrict__ kin) {
    __shared__ float  ss[4096];
    __shared__ float2 sA[2048];
    int ch = blockIdx.x;
    int t = threadIdx.x;
    bool isK = (ch < 128);
    const float* src = isK ? (kin + ch*4096) : (f + (ch-128)*4096);
    for (int i = t; i < 4096; i += 512) ss[i] = src[i];
    __syncthreads();
    if (isK) {
        float rv[8];
        #pragma unroll
        for (int r = 0; r < 8; r++) {
            int idx = t + 512*r;
            int a = idx >> 6, b = idx & 63;
            int na = (64 - a) & 63, nb = (64 - b) & 63;
            rv[r] = (ss[a*64 + b]  + ss[nb*64 + a] + ss[na*64 + nb] + ss[b*64 + na]
                   + ss[b*64 + a]  + ss[a*64 + nb] + ss[nb*64 + na] + ss[na*64 + b]) * 0.125f;
        }
        __syncthreads();
        #pragma unroll
        for (int r = 0; r < 8; r++) ss[t + 512*r] = rv[r];
        __syncthreads();
    }
    int k2 = t & 31, grp = t >> 5;
    {
        float2 acc[4];
        #pragma unroll
        for (int r = 0; r < 4; r++) acc[r] = make_float2(0.f, 0.f);
        for (int y = 0; y < 64; y++) {
            float2 e = g_Ey[y*32 + k2];
            #pragma unroll
            for (int r = 0; r < 4; r++) {
                float sv = ss[(grp*4 + r)*64 + y];
                acc[r].x = fmaf(sv, e.x, acc[r].x);
                acc[r].y = fmaf(sv, e.y, acc[r].y);
            }
        }
        #pragma unroll
        for (int r = 0; r < 4; r++) sA[(grp*4 + r)*32 + k2] = acc[r];
    }
    __syncthreads();
    {
        float2 acc[4];
        #pragma unroll
        for (int r = 0; r < 4; r++) acc[r] = make_float2(0.f, 0.f);
        for (int x = 0; x < 64; x++) {
            #pragma unroll
            for (int r = 0; r < 4; r++) {
                int m = grp*4 + r;
                float2 e = g_Ex[m*64 + x];
                float2 a = sA[x*32 + k2];
                acc[r].x = fmaf(e.x, a.x, fmaf(-e.y, a.y, acc[r].x));
                acc[r].y = fmaf(e.x, a.y, fmaf( e.y, a.x, acc[r].y));
            }
        }
        float2* dstF = isK ? (g_Kf + ch*NF) : (g_Ff + (ch-128)*NF);
        #pragma unroll
        for (int r = 0; r < 4; r++) {
            int m = grp*4 + r;
            if (m < 63) dstF[m*32 + k2] = acc[r];
        }
    }
}

// ---------------- channel contraction (float4 vectorized) ----------------
__global__ void k_conv() {
    int idx = blockIdx.x * 256 + threadIdx.x;       // 0 .. 258047
    int mk2 = idx % 1008;
    int bj  = idx / 1008;
    int b = bj >> 4, j = bj & 15;
    float4 acc = make_float4(0.f, 0.f, 0.f, 0.f);
    #pragma unroll
    for (int i = 0; i < 8; i++) {
        float4 Fv = *(const float4*)&g_Ff[(b*8 + i)*NF + mk2*2];
        float4 Kv = *(const float4*)&g_Kf[(i*16 + j)*NF + mk2*2];
        acc.x = fmaf(Fv.x, Kv.x, fmaf(-Fv.y, Kv.y, acc.x));
        acc.y = fmaf(Fv.x, Kv.y, fmaf( Fv.y, Kv.x, acc.y));
        acc.z = fmaf(Fv.z, Kv.z, fmaf(-Fv.w, Kv.w, acc.z));
        acc.w = fmaf(Fv.z, Kv.w, fmaf( Fv.w, Kv.z, acc.w));
    }
    *(float4*)&g_Cf[bj*NF + mk2*2] = acc;
}

// ---------------- fused inverse transform: 2 quarters/block, f32x2 --------
#define SM2_SD   0
#define SM2_Z    15872
#define SM2_Q    16128
#define SM2_TOT  (16128 + 8704)

__global__ void __launch_bounds__(128, 5) k_itrans(float* __restrict__ out) {
    extern __shared__ char sm[];
    float4* SD = (float4*)(sm + SM2_SD);      // [(k1-1)*32 + k2]
    float2* Zs = (float2*)(sm + SM2_Z);
    float2* Qs = (float2*)(sm + SM2_Q);       // [k2*34 + j]

    int t = threadIdx.x;
    int ch = blockIdx.x >> 1, qh = blockIdx.x & 1;
    const float2* src; float* dst; const float* mul = nullptr; float msgn = 1.0f;
    if (ch < 128) {
        src = g_Ff + ch*NF;
        int b = ch >> 3, c = ch & 7;
        dst = out + (size_t)(b*128 + c) * NPIX;
    } else if (ch < 384) {
        int c2 = ch - 128; src = g_Cf + c2*NF; dst = g_u + (size_t)c2*NPIX; mul = g_MU;
    } else {
        int c2 = ch - 384; src = g_Cf + c2*NF; dst = g_v + (size_t)c2*NPIX; mul = g_MV; msgn = -1.0f;
    }

    // phase 1: build S/D from global (once per block)
    for (int e = t; e < 992; e += 128) {
        int k1 = (e >> 5) + 1, k2 = e & 31;
        float2 gp = src[(31 + k1)*32 + k2];
        float2 gm = src[(31 - k1)*32 + k2];
        float2 a, b;
        if (mul) {
            float m = mul[(31 + k1)*32 + k2];
            a = make_float2(-m*gp.y, m*gp.x);
            float mm = msgn * m;
            b = make_float2(-mm*gm.y, mm*gm.x);
        } else {
            a = gp; b = gm;
        }
        SD[e] = make_float4(a.x + b.x, a.y + b.y, a.x - b.x, a.y - b.y);
    }
    if (t < 32) {
        float2 z = src[31*32 + t];
        if (mul) {
            float m = mul[31*32 + t];
            z = make_float2(-m*z.y, m*z.x);
        }
        Zs[t] = z;
    }
    __syncthreads();

    #pragma unroll 1
    for (int qi = 0; qi < 2; qi++) {
        int qt = qh*2 + qi;

        // phase 2a: Q[k2][n1=64] (qt==0 only)
        if (qt == 0 && t < 32) {
            float2 z = Zs[t];
            float pr = z.x, pi = z.y;
            #pragma unroll
            for (int k1 = 1; k1 < 32; k1++) {
                float4 sd = SD[(k1-1)*32 + t];
                float sgn = (k1 & 1) ? -1.0f : 1.0f;
                pr = fmaf(sgn, sd.x, pr);
                pi = fmaf(sgn, sd.y, pi);
            }
            Qs[t*34 + 32] = make_float2(pr, pi);
        }

        // phase 2b: stage1 — one n1h x 4 k2; packed (P,T)/(U,R) FFMA2
        {
            int jl = t & 15, kg = t >> 4, k2b = kg*4;
            int n1 = qt*16 + jl;
            u64 PT[4], UR[4];
            #pragma unroll
            for (int u = 0; u < 4; u++) { PT[u] = 0ULL; UR[u] = 0ULL; }
            float2 step = g_WxT[32*128 + n1];
            float2 w = step;
            float4 s0 = SD[k2b+0], s1 = SD[k2b+1], s2 = SD[k2b+2], s3 = SD[k2b+3];
            #pragma unroll
            for (int k1 = 1; k1 <= 31; k1++) {
                float4 c0 = s0, c1 = s1, c2 = s2, c3 = s3;
                float2 wc = w;
                if (k1 < 31) {
                    const float4* p = SD + k1*32 + k2b;
                    s0 = p[0]; s1 = p[1]; s2 = p[2]; s3 = p[3];
                    float wx = fmaf(wc.x, step.x, -wc.y*step.y);
                    float wy = fmaf(wc.x, step.y,  wc.y*step.x);
                    w = make_float2(wx, wy);
                }
                u64 wxx = pk2(wc.x, wc.x), wyy = pk2(wc.y, wc.y);
                PT[0] = fma2(wxx, pk2(c0.x, c0.y), PT[0]);  UR[0] = fma2(wyy, pk2(c0.z, c0.w), UR[0]);
                PT[1] = fma2(wxx, pk2(c1.x, c1.y), PT[1]);  UR[1] = fma2(wyy, pk2(c1.z, c1.w), UR[1]);
                PT[2] = fma2(wxx, pk2(c2.x, c2.y), PT[2]);  UR[2] = fma2(wyy, pk2(c2.z, c2.w), UR[2]);
                PT[3] = fma2(wxx, pk2(c3.x, c3.y), PT[3]);  UR[3] = fma2(wyy, pk2(c3.z, c3.w), UR[3]);
            }
            #pragma unroll
            for (int u = 0; u < 4; u++) {
                int k2 = k2b + u;
                float2 z = Zs[k2];
                float P, T, U, R;
                upk2(PT[u], P, T);
                upk2(UR[u], U, R);
                Qs[k2*34 + jl]      = make_float2(z.x + P - R, z.y + T + U);
                Qs[k2*34 + 16 + jl] = make_float2(z.x + P + R, z.y + T - U);
            }
        }
        __syncthreads();

        // phase 3a: n2 = 64 column
        if (t < 32) {
            int j = t;
            int n1row = (j < 16) ? (qt*16 + j) : ((128 - (qt*16 + j - 16)) & 127);
            float acc = 0.f;
            #pragma unroll
            for (int k2 = 0; k2 < 32; k2++)
                acc = fmaf(g_WyT[k2*128 + 64].x, Qs[k2*34 + j].x, acc);
            dst[n1row*128 + 64] = acc;
        } else if (qt == 0 && t == 32) {
            float acc = 0.f;
            #pragma unroll
            for (int k2 = 0; k2 < 32; k2++)
                acc = fmaf(g_WyT[k2*128 + 64].x, Qs[k2*34 + 32].x, acc);
            dst[64*128 + 64] = acc;
        }

        // phase 3b: stage2 — packed accumulators + packed phase recurrence
        {
            int tx = t & 15, ty = t >> 4;
            int jb = ty*4;
            const float S = 1.0f/4096.0f;
            u64 A01[4], A23[4], B01[4], B23[4];
            {
                float4 q01 = *(const float4*)&Qs[jb];
                float4 q23 = *(const float4*)&Qs[jb + 2];
                A01[0] = A23[0] = pk2(0.5f*q01.x, 0.5f*q01.x);
                A01[1] = A23[1] = pk2(0.5f*q01.z, 0.5f*q01.z);
                A01[2] = A23[2] = pk2(0.5f*q23.x, 0.5f*q23.x);
                A01[3] = A23[3] = pk2(0.5f*q23.z, 0.5f*q23.z);
                #pragma unroll
                for (int u = 0; u < 4; u++) { B01[u] = 0ULL; B23[u] = 0ULL; }
            }
            float2 st0 = g_WxT[32*128 + tx*4 + 0];
            float2 st1 = g_WxT[32*128 + tx*4 + 1];
            float2 st2 = g_WxT[32*128 + tx*4 + 2];
            float2 st3 = g_WxT[32*128 + tx*4 + 3];
            u64 SX01 = pk2(st0.x, st1.x), SX23 = pk2(st2.x, st3.x);
            u64 SY01 = pk2(st0.y, st1.y), SY23 = pk2(st2.y, st3.y);
            u64 NY01 = pk2(-st0.y, -st1.y), NY23 = pk2(-st2.y, -st3.y);
            u64 X01 = SX01, X23 = SX23, Y01 = SY01, Y23 = SY23;
            float4 q01 = *(const float4*)&Qs[34 + jb];
            float4 q23 = *(const float4*)&Qs[34 + jb + 2];
            #pragma unroll
            for (int k2 = 1; k2 <= 31; k2++) {
                float4 qc01 = q01, qc23 = q23;
                u64 cX01 = X01, cX23 = X23, cY01 = Y01, cY23 = Y23;
                if (k2 < 31) {
                    q01 = *(const float4*)&Qs[(k2+1)*34 + jb];
                    q23 = *(const float4*)&Qs[(k2+1)*34 + jb + 2];
                    X01 = fma2(cX01, SX01, mul2(cY01, NY01));
                    Y01 = fma2(cX01, SY01, mul2(cY01, SX01));
                    X23 = fma2(cX23, SX23, mul2(cY23, NY23));
                    Y23 = fma2(cX23, SY23, mul2(cY23, SX23));
                }
                u64 qr0 = pk2(qc01.x, qc01.x), qi0 = pk2(qc01.y, qc01.y);
                u64 qr1 = pk2(qc01.z, qc01.z), qi1 = pk2(qc01.w, qc01.w);
                u64 qr2 = pk2(qc23.x, qc23.x), qi2 = pk2(qc23.y, qc23.y);
                u64 qr3 = pk2(qc23.z, qc23.z), qi3 = pk2(qc23.w, qc23.w);
                A01[0] = fma2(qr0, cX01, A01[0]);  A23[0] = fma2(qr0, cX23, A23[0]);
                B01[0] = fma2(qi0, cY01, B01[0]);  B23[0] = fma2(qi0, cY23, B23[0]);
                A01[1] = fma2(qr1, cX01, A01[1]);  A23[1] = fma2(qr1, cX23, A23[1]);
                B01[1] = fma2(qi1, cY01, B01[1]);  B23[1] = fma2(qi1, cY23, B23[1]);
                A01[2] = fma2(qr2, cX01, A01[2]);  A23[2] = fma2(qr2, cX23, A23[2]);
                B01[2] = fma2(qi2, cY01, B01[2]);  B23[2] = fma2(qi2, cY23, B23[2]);
                A01[3] = fma2(qr3, cX01, A01[3]);  A23[3] = fma2(qr3, cX23, A23[3]);
                B01[3] = fma2(qi3, cY01, B01[3]);  B23[3] = fma2(qi3, cY23, B23[3]);
            }
            #pragma unroll
            for (int u = 0; u < 4; u++) {
                int j = jb + u;
                int n1row = (j < 16) ? (qt*16 + j) : ((128 - (qt*16 + j - 16)) & 127);
                float* row = dst + n1row*128;
                float a0, a1, a2, a3, b0, b1, b2, b3;
                upk2(A01[u], a0, a1); upk2(A23[u], a2, a3);
                upk2(B01[u], b0, b1); upk2(B23[u], b2, b3);
                *(float4*)(row + tx*4) = make_float4(S*(a0-b0), S*(a1-b1), S*(a2-b2), S*(a3-b3));
                row[(128 - (tx*4 + 0)) & 127] = S*(a0+b0);
                row[(128 - (tx*4 + 1)) & 127] = S*(a1+b1);
                row[(128 - (tx*4 + 2)) & 127] = S*(a2+b2);
                row[(128 - (tx*4 + 3)) & 127] = S*(a3+b3);
            }
        }

        // phase 3c: output row n1 = 64 (qt==0 only)
        if (qt == 0) {
            int n2 = t;
            float acc = 0.f;
            #pragma unroll 4
            for (int k2 = 0; k2 < 32; k2++) {
                float2 q = Qs[k2*34 + 32];
                float2 w = g_WyT[k2*128 + n2];
                acc = fmaf(q.x, w.x, fmaf(-q.y, w.y, acc));
            }
            if (n2 != 64) dst[64*128 + n2] = acc;
        }
        __syncthreads();   // protect Qs reuse for next quarter
    }
}

// ---------------- cross products (streaming stores) ----------------
__global__ void __launch_bounds__(128) k_cross(float* __restrict__ out) {
    __shared__ float us[16*128], vs[16*128];
    int b = blockIdx.x >> 7, n1 = blockIdx.x & 127;
    int t = threadIdx.x;
    for (int i = t; i < 16*128; i += 128) {
        int c = i >> 7, n2 = i & 127;
        us[i] = g_u[((size_t)(b*16 + c)*128 + n1)*128 + n2];
        vs[i] = g_v[((size_t)(b*16 + c)*128 + n1)*128 + n2];
    }
    __syncthreads();
    int q = t & 31, g = t >> 5;
    float* obase = out + ((size_t)b*128 + 8)*NPIX + n1*128 + q*4;
    #pragma unroll 2
    for (int pp = 0; pp < 30; pp++) {
        int p = g*30 + pp;
        int i = g_I[p], j = g_J[p];
        float4 ui = *(float4*)&us[i*128 + q*4];
        float4 vj = *(float4*)&vs[j*128 + q*4];
        float4 uj = *(float4*)&us[j*128 + q*4];
        float4 vi = *(float4*)&vs[i*128 + q*4];
        float4 r;
        r.x = ui.x*vj.x - uj.x*vi.x;
        r.y = ui.y*vj.y - uj.y*vi.y;
        r.z = ui.z*vj.z - uj.z*vi.z;
        r.w = ui.w*vj.w - uj.w*vi.w;
        __stcs((float4*)(obase + (size_t)p*NPIX), r);
    }
}

// ---------------- launch ----------------
extern "C" void kernel_launch(void* const* d_in, const int* in_sizes, int n_in,
                              void* d_out, int out_size) {
    const float* f    = (const float*)d_in[0];   // [16,8,64,64]
    const float* kern = (const float*)d_in[1];   // [1,8,16,64,64]
    float* out = (float*)d_out;                  // [16,128,128,128]
    (void)in_sizes; (void)n_in; (void)out_size;

    cudaFuncSetAttribute(k_itrans, cudaFuncAttributeMaxDynamicSharedMemorySize, SM2_TOT);

    k_init   <<<40,   256>>>();
    k_fft64  <<<256,  512>>>(f, kern);
    k_conv   <<<1008, 256>>>();
    k_itrans <<<1280, 128, SM2_TOT>>>(out);
    k_cross  <<<2048, 128>>>(out);
}